// round 5
// baseline (speedup 1.0000x reference)
#include <cuda_runtime.h>
#include <cuda_bf16.h>
#include <cstdint>

// ---------------- problem constants ----------------
#define KTOT 784            // 28*28 GEMM K
#define NHID 200            // hidden width
#define NPAD 216            // N padded to 27*8 (3-way split of 72 = 9*8)
#define NCLS 10
#define BM   128            // rows per CTA
#define BK   64             // K per chunk
#define NCHUNK 13           // 12*64 + 16 (last chunk: 1 k-step)
#define ROWB 144            // bytes per bf16 row -> LDSM conflict-free
#define ACH  (BM * ROWB)    // 18432 per term
#define BCH  (NPAD * ROWB)  // 31104 per term
#define NTHREADS 512        // 12 consumer warps + 4 producer warps

// ---------------- smem layout (bytes) ----------------
#define SM_FULL0  0
#define SM_FULL1  8
#define SM_EMPTY0 16
#define SM_EMPTY1 24
#define SM_W2     64                        // 2000 floats
#define SM_B1     8064                      // 200 floats
#define SM_B2     8864                      // 10 floats
#define SM_ABASE  9216
#define SM_A(s, t) (SM_ABASE + ((s) * 2 + (t)) * ACH)          // 4 x 18432
#define SM_BBASE  (SM_ABASE + 4 * ACH)                         // 82944
#define SM_B(s, t) (SM_BBASE + ((s) * 2 + (t)) * BCH)          // 4 x 31104
#define SMEM_TOTAL (SM_BBASE + 4 * BCH)                        // 207360
// epilogue reuse
#define SM_HID    9216                      // 128 x 210 floats
#define HSTRIDE   210
#define SM_OUTP   (SM_HID + BM * HSTRIDE * 4)

// Per-chunk images of W1eff^T (n-major rows, 144B stride) in bf16 hi/lo.
__device__ __align__(16) unsigned char g_wB_hi[NCHUNK * BCH];
__device__ __align__(16) unsigned char g_wB_lo[NCHUNK * BCH];

// ---------------- PTX helpers ----------------
__device__ __forceinline__ uint32_t smem_u32(const void* p) {
    uint32_t a;
    asm("{ .reg .u64 t; cvta.to.shared.u64 t, %1; cvt.u32.u64 %0, t; }" : "=r"(a) : "l"(p));
    return a;
}

#define MBARRIER_INIT(a, n) \
    asm volatile("mbarrier.init.shared.b64 [%0], %1;" :: "r"(a), "r"((uint32_t)(n)) : "memory")
#define MBARRIER_EXPECT_TX(a, b) \
    asm volatile("mbarrier.arrive.expect_tx.shared.b64 _, [%0], %1;" :: "r"(a), "r"((uint32_t)(b)) : "memory")
#define MBARRIER_ARRIVE(a) \
    asm volatile("mbarrier.arrive.shared.b64 _, [%0];" :: "r"(a) : "memory")

#define MBARRIER_WAIT_PARITY(mbar, par) do {                                   \
    uint32_t _m = (mbar), _p = (par), _d;                                      \
    asm volatile("{\n\t.reg .pred p;\n\t"                                      \
        "mbarrier.try_wait.parity.acquire.cta.shared::cta.b64 p, [%1], %2;\n\t"\
        "selp.b32 %0, 1, 0, p;\n\t}"                                           \
        : "=r"(_d) : "r"(_m), "r"(_p) : "memory");                             \
    if (!_d) {                                                                 \
        asm volatile("{\n\t.reg .pred P1;\n\t"                                 \
            "W%=:\n\t"                                                         \
            "mbarrier.try_wait.parity.acquire.cta.shared::cta.b64 P1, [%0], %1, 0x989680;\n\t" \
            "@P1 bra.uni D%=;\n\t"                                             \
            "bra.uni W%=;\n\t"                                                 \
            "D%=:\n\t}" :: "r"(_m), "r"(_p) : "memory");                       \
    }                                                                          \
} while (0)

__device__ __forceinline__ void bulk_g2s(uint32_t dst, const void* src, uint32_t bytes, uint32_t mbar) {
    asm volatile("cp.async.bulk.shared::cta.global.mbarrier::complete_tx::bytes [%0], [%1], %2, [%3];"
        :: "r"(dst), "l"(src), "r"(bytes), "r"(mbar) : "memory");
}

__device__ __forceinline__ void ldsm4(uint32_t* d, uint32_t addr) {
    asm volatile("ldmatrix.sync.aligned.m8n8.x4.shared.b16 {%0,%1,%2,%3}, [%4];"
        : "=r"(d[0]), "=r"(d[1]), "=r"(d[2]), "=r"(d[3]) : "r"(addr));
}
__device__ __forceinline__ void ldsm2(uint32_t* d, uint32_t addr) {
    asm volatile("ldmatrix.sync.aligned.m8n8.x2.shared.b16 {%0,%1}, [%2];"
        : "=r"(d[0]), "=r"(d[1]) : "r"(addr));
}
__device__ __forceinline__ void mma16816(float* c, const uint32_t* a, const uint32_t* b) {
    asm volatile("mma.sync.aligned.m16n8k16.row.col.f32.bf16.bf16.f32 "
        "{%0,%1,%2,%3}, {%4,%5,%6,%7}, {%8,%9}, {%0,%1,%2,%3};"
        : "+f"(c[0]), "+f"(c[1]), "+f"(c[2]), "+f"(c[3])
        : "r"(a[0]), "r"(a[1]), "r"(a[2]), "r"(a[3]), "r"(b[0]), "r"(b[1]));
}

// ---------------------------------------------------------------------------
// Prep: W1eff[k][n] = conv folded into w1; transposed [n][k] rows, bf16 hi
// (truncation) + bf16 lo (rn of residual), 144B row stride, per-chunk images.
// ---------------------------------------------------------------------------
__global__ void prep_kernel(const float* __restrict__ conv_w, const float* __restrict__ w1) {
    int p = blockIdx.x;    // k: 0..831
    int h = threadIdx.x;   // n: 0..215
    float s = 0.f;
    if (p < KTOT && h < NHID) {
        int y = p / 28, xx = p % 28;
#pragma unroll
        for (int di = 0; di < 3; ++di) {
            int oy = y - di;
            if (oy < 0 || oy > 25) continue;
#pragma unroll
            for (int dj = 0; dj < 3; ++dj) {
                int ox = xx - dj;
                if (ox < 0 || ox > 25) continue;
                s += conv_w[di * 3 + dj] * w1[(oy * 26 + ox) * NHID + h];
            }
        }
    }
    uint32_t sbits = __float_as_uint(s);
    uint32_t hib = sbits & 0xFFFF0000u;
    float r = s - __uint_as_float(hib);
    __nv_bfloat16 lo16 = __float2bfloat16(r);
    unsigned short lo_us = *reinterpret_cast<unsigned short*>(&lo16);

    int chunk = p >> 6, kl = p & 63;
    size_t off = (size_t)chunk * BCH + (size_t)h * ROWB + (size_t)kl * 2;
    *(unsigned short*)(g_wB_hi + off) = (unsigned short)(hib >> 16);
    *(unsigned short*)(g_wB_lo + off) = lo_us;
}

// Split 8 fp32 into bf16-hi (trunc) + bf16-lo (rn residual), packed pairs.
__device__ __forceinline__ void split8(float4 v0, float4 v1, uint4& hi, uint4& lo) {
    uint32_t a[8] = {__float_as_uint(v0.x), __float_as_uint(v0.y), __float_as_uint(v0.z), __float_as_uint(v0.w),
                     __float_as_uint(v1.x), __float_as_uint(v1.y), __float_as_uint(v1.z), __float_as_uint(v1.w)};
    uint32_t rb[8];
#pragma unroll
    for (int i = 0; i < 8; ++i) {
        float t = __uint_as_float(a[i] & 0xFFFF0000u);
        float res = __uint_as_float(a[i]) - t;
        __nv_bfloat16 lb = __float2bfloat16(res);
        rb[i] = (uint32_t)(*reinterpret_cast<unsigned short*>(&lb)) << 16;
    }
    hi.x = __byte_perm(a[0], a[1], 0x7632); hi.y = __byte_perm(a[2], a[3], 0x7632);
    hi.z = __byte_perm(a[4], a[5], 0x7632); hi.w = __byte_perm(a[6], a[7], 0x7632);
    lo.x = __byte_perm(rb[0], rb[1], 0x7632); lo.y = __byte_perm(rb[2], rb[3], 0x7632);
    lo.z = __byte_perm(rb[4], rb[5], 0x7632); lo.w = __byte_perm(rb[6], rb[7], 0x7632);
}

// ---------------------------------------------------------------------------
// Fused: out = relu(X @ W1eff + b1) @ w2 + b2  (split-bf16 mma.sync)
// Warp-specialized: warps 0-11 = consumers (4m x 3n, tile 32x72),
//                   warps 12-15 = producers (A convert + B bulk copies).
// ---------------------------------------------------------------------------
__global__ __launch_bounds__(NTHREADS, 1)
void fused_mma_kernel(const float* __restrict__ x,
                      const float* __restrict__ b1,
                      const float* __restrict__ w2,
                      const float* __restrict__ b2,
                      float* __restrict__ out) {
    extern __shared__ __align__(1024) unsigned char smem[];
    const uint32_t sb = smem_u32(smem);
    const int tid  = threadIdx.x;
    const int wid  = tid >> 5;
    const int lane = tid & 31;
    const int m0   = blockIdx.x * BM;

    float* w2s = (float*)(smem + SM_W2);
    float* b1s = (float*)(smem + SM_B1);
    float* b2s = (float*)(smem + SM_B2);

    if (tid == 0) {
        MBARRIER_INIT(sb + SM_FULL0, 128);   // 127 producer arrives + 1 expect_tx
        MBARRIER_INIT(sb + SM_FULL1, 128);
        MBARRIER_INIT(sb + SM_EMPTY0, 384);  // all consumer threads
        MBARRIER_INIT(sb + SM_EMPTY1, 384);
    }
    for (int e = tid; e < NHID * NCLS; e += NTHREADS) w2s[e] = w2[e];
    for (int e = tid; e < NHID; e += NTHREADS)        b1s[e] = b1[e];
    if (tid < NCLS)                                   b2s[tid] = b2[tid];
    __syncthreads();   // mbarrier init + w2s visible to all

    float acc[72];
#pragma unroll
    for (int i = 0; i < 72; ++i) acc[i] = 0.f;

    if (wid >= 12) {
        // ================= producers =================
        const int ptid = tid - 384;   // 0..127
#pragma unroll 1
        for (int i = 0; i < NCHUNK; ++i) {
            const int s = i & 1;
            const uint32_t full  = sb + (s ? SM_FULL1 : SM_FULL0);
            const uint32_t empty = sb + (s ? SM_EMPTY1 : SM_EMPTY0);
            if (i >= 2) MBARRIER_WAIT_PARITY(empty, ((i - 2) >> 1) & 1);

            const int k0 = i * BK;
            unsigned char* Ahi = smem + SM_A(s, 0);
            unsigned char* Alo = smem + SM_A(s, 1);
#pragma unroll
            for (int it = 0; it < 8; ++it) {
                int t = ptid + it * 128;       // 0..1023
                int m = t >> 3, g = t & 7;
                int kg = k0 + g * 8;
                uint4 hi = {0, 0, 0, 0}, lo = {0, 0, 0, 0};
                if (kg < KTOT) {
                    const float4* src = (const float4*)(x + (size_t)(m0 + m) * KTOT + kg);
                    split8(src[0], src[1], hi, lo);
                }
                uint32_t so = (uint32_t)m * ROWB + (uint32_t)g * 16;
                *(uint4*)(Ahi + so) = hi;
                *(uint4*)(Alo + so) = lo;
            }
            if (ptid == 0) {
                MBARRIER_EXPECT_TX(full, 2 * BCH);
                bulk_g2s(sb + SM_B(s, 0), g_wB_hi + (size_t)i * BCH, BCH, full);
                bulk_g2s(sb + SM_B(s, 1), g_wB_lo + (size_t)i * BCH, BCH, full);
            } else {
                MBARRIER_ARRIVE(full);
            }
        }
    } else {
        // ================= consumers =================
        const int wm = (wid & 3) * 32;      // 4 m-groups
        const int wn = (wid >> 2) * 72;     // 3 n-groups
        const int lg = lane >> 3, lr = lane & 7;
        const uint32_t a_off = (uint32_t)(((lg & 1) * 8 + lr) * ROWB + (lg >> 1) * 16);
        const uint32_t b_off = (uint32_t)(((lg >> 1) * 8 + lr) * ROWB + (lg & 1) * 16);

#pragma unroll 1
        for (int i = 0; i < NCHUNK; ++i) {
            const int s = i & 1;
            MBARRIER_WAIT_PARITY(sb + (s ? SM_FULL1 : SM_FULL0), (i >> 1) & 1);

            const uint32_t aHiB = sb + SM_A(s, 0) + (uint32_t)wm * ROWB + a_off;
            const uint32_t aLoB = sb + SM_A(s, 1) + (uint32_t)wm * ROWB + a_off;
            const uint32_t bHiB = sb + SM_B(s, 0) + (uint32_t)wn * ROWB + b_off;
            const uint32_t bLoB = sb + SM_B(s, 1) + (uint32_t)wn * ROWB + b_off;

#pragma unroll
            for (int ks = 0; ks < 4; ++ks) {
                if (i == NCHUNK - 1 && ks > 0) break;   // last chunk: 16 valid k
                const uint32_t kb = (uint32_t)ks * 32;
                uint32_t bf[18], ah[8], al[8];

                // B_hi fragments (9 n-granules)
#pragma unroll
                for (int tp = 0; tp < 4; ++tp) ldsm4(&bf[tp * 4], bHiB + tp * (16 * ROWB) + kb);
                ldsm2(&bf[16], bHiB + 4 * (16 * ROWB) + kb);
                // A fragments (32 rows, hi + lo)
                ldsm4(&ah[0], aHiB + kb);
                ldsm4(&ah[4], aHiB + 16 * ROWB + kb);
                ldsm4(&al[0], aLoB + kb);
                ldsm4(&al[4], aLoB + 16 * ROWB + kb);

                // term 1: A_hi x B_hi
#pragma unroll
                for (int tn = 0; tn < 9; ++tn) {
                    mma16816(&acc[tn * 4],      &ah[0], &bf[tn * 2]);
                    mma16816(&acc[36 + tn * 4], &ah[4], &bf[tn * 2]);
                }
                // term 2: A_lo x B_hi
#pragma unroll
                for (int tn = 0; tn < 9; ++tn) {
                    mma16816(&acc[tn * 4],      &al[0], &bf[tn * 2]);
                    mma16816(&acc[36 + tn * 4], &al[4], &bf[tn * 2]);
                }
                // B_lo fragments (reuse bf)
#pragma unroll
                for (int tp = 0; tp < 4; ++tp) ldsm4(&bf[tp * 4], bLoB + tp * (16 * ROWB) + kb);
                ldsm2(&bf[16], bLoB + 4 * (16 * ROWB) + kb);
                // term 3: A_hi x B_lo
#pragma unroll
                for (int tn = 0; tn < 9; ++tn) {
                    mma16816(&acc[tn * 4],      &ah[0], &bf[tn * 2]);
                    mma16816(&acc[36 + tn * 4], &ah[4], &bf[tn * 2]);
                }
            }
            MBARRIER_ARRIVE(sb + (s ? SM_EMPTY1 : SM_EMPTY0));
        }
    }
    __syncthreads();   // all MMA + TMA consumed; safe to repurpose smem

    // ---------------- epilogue: relu(+b1) -> smem, then @ w2 + b2 ----------------
    float* hid  = (float*)(smem + SM_HID);    // [128][210]
    float* outp = (float*)(smem + SM_OUTP);   // [128][10]

    if (wid < 12) {
        const int wm = (wid & 3) * 32;
        const int wn = (wid >> 2) * 72;
#pragma unroll
        for (int tm = 0; tm < 2; ++tm) {
#pragma unroll
            for (int tn = 0; tn < 9; ++tn) {
                int c = wn + tn * 8 + (lane & 3) * 2;
                if (c < NHID) {
                    int r0 = wm + tm * 16 + (lane >> 2);
                    float b1a = b1s[c], b1b = b1s[c + 1];
                    const float* a = &acc[tm * 36 + tn * 4];
                    hid[r0 * HSTRIDE + c]           = fmaxf(a[0] + b1a, 0.f);
                    hid[r0 * HSTRIDE + c + 1]       = fmaxf(a[1] + b1b, 0.f);
                    hid[(r0 + 8) * HSTRIDE + c]     = fmaxf(a[2] + b1a, 0.f);
                    hid[(r0 + 8) * HSTRIDE + c + 1] = fmaxf(a[3] + b1b, 0.f);
                }
            }
        }
    }
    for (int e = tid; e < BM * NCLS; e += NTHREADS) outp[e] = 0.f;
    __syncthreads();

    {
        int m  = tid >> 2;                  // 0..127
        int h0 = (tid & 3) * 50;            // 4 k-slices of 50
        float p[NCLS];
#pragma unroll
        for (int c = 0; c < NCLS; ++c) p[c] = 0.f;
        for (int h = h0; h < h0 + 50; ++h) {
            float v = hid[m * HSTRIDE + h];
#pragma unroll
            for (int c = 0; c < NCLS; ++c) p[c] += v * w2s[h * NCLS + c];
        }
#pragma unroll
        for (int c = 0; c < NCLS; ++c) atomicAdd(&outp[m * NCLS + c], p[c]);
    }
    __syncthreads();

    for (int e = tid; e < BM * NCLS; e += NTHREADS)
        out[(size_t)m0 * NCLS + e] = outp[e] + b2s[e % NCLS];
}

// ---------------------------------------------------------------------------
extern "C" void kernel_launch(void* const* d_in, const int* in_sizes, int n_in,
                              void* d_out, int out_size) {
    const float* x      = (const float*)d_in[0];   // [65536, 784]
    const float* conv_w = (const float*)d_in[1];   // [3, 3]
    const float* w1     = (const float*)d_in[2];   // [676, 200]
    const float* b1     = (const float*)d_in[3];   // [200]
    const float* w2     = (const float*)d_in[4];   // [200, 10]
    const float* b2     = (const float*)d_in[5];   // [10]
    float* out          = (float*)d_out;           // [65536, 10]

    cudaFuncSetAttribute(fused_mma_kernel,
                         cudaFuncAttributeMaxDynamicSharedMemorySize, SMEM_TOTAL);

    prep_kernel<<<NCHUNK * BK, NPAD>>>(conv_w, w1);
    fused_mma_kernel<<<65536 / BM, NTHREADS, SMEM_TOTAL>>>(x, b1, w2, b2, out);
}

// round 6
// speedup vs baseline: 1.3612x; 1.3612x over previous
#include <cuda_runtime.h>
#include <cuda_bf16.h>
#include <cstdint>

// ---------------- problem constants ----------------
#define KTOT 784            // 28*28 GEMM K
#define NHID 200            // hidden width
#define NPAD 208            // N padded to 26*8
#define NCLS 10
#define BM   128            // rows per CTA
#define BK   64             // K per chunk
#define NCHUNK 13           // 12*64 + 16 (last chunk: 1 k-step)
#define ROWB 144            // bytes per bf16 row -> LDSM conflict-free
#define ACH  (BM * ROWB)    // 18432 per term
#define BCH  (NPAD * ROWB)  // 29952 per term
#define NTHREADS 512

// ---------------- smem layout (bytes) ----------------
#define SM_MB0   0
#define SM_MB1   8
#define SM_W2    64                         // 2000 floats
#define SM_B1    8064                       // 200 floats
#define SM_B2    8864                       // 10 floats
#define SM_ABASE 9216
#define SM_A(s, t) (SM_ABASE + ((s) * 2 + (t)) * ACH)          // 4 x 18432
#define SM_BBASE (SM_ABASE + 4 * ACH)                          // 82944
#define SM_B(s, t) (SM_BBASE + ((s) * 2 + (t)) * BCH)          // 4 x 29952
#define SMEM_TOTAL (SM_BBASE + 4 * BCH)                        // 202752
// epilogue reuse
#define SM_HID   9216                       // 128 x 210 floats
#define HSTRIDE  210
#define SM_OUTP  (SM_HID + BM * HSTRIDE * 4)

// Per-chunk images of W1eff^T (n-major rows, 144B stride) in bf16 hi/lo.
__device__ __align__(16) unsigned char g_wB_hi[NCHUNK * BCH];
__device__ __align__(16) unsigned char g_wB_lo[NCHUNK * BCH];

// ---------------- PTX helpers ----------------
__device__ __forceinline__ uint32_t smem_u32(const void* p) {
    uint32_t a;
    asm("{ .reg .u64 t; cvta.to.shared.u64 t, %1; cvt.u32.u64 %0, t; }" : "=r"(a) : "l"(p));
    return a;
}

#define MBARRIER_INIT(a, n) \
    asm volatile("mbarrier.init.shared.b64 [%0], %1;" :: "r"(a), "r"((uint32_t)(n)) : "memory")
#define MBARRIER_EXPECT_TX(a, b) \
    asm volatile("mbarrier.arrive.expect_tx.shared.b64 _, [%0], %1;" :: "r"(a), "r"((uint32_t)(b)) : "memory")

#define MBARRIER_WAIT_PARITY(mbar, par) do {                                   \
    uint32_t _m = (mbar), _p = (par), _d;                                      \
    asm volatile("{\n\t.reg .pred p;\n\t"                                      \
        "mbarrier.try_wait.parity.acquire.cta.shared::cta.b64 p, [%1], %2;\n\t"\
        "selp.b32 %0, 1, 0, p;\n\t}"                                           \
        : "=r"(_d) : "r"(_m), "r"(_p) : "memory");                             \
    if (!_d) {                                                                 \
        asm volatile("{\n\t.reg .pred P1;\n\t"                                 \
            "W%=:\n\t"                                                         \
            "mbarrier.try_wait.parity.acquire.cta.shared::cta.b64 P1, [%0], %1, 0x989680;\n\t" \
            "@P1 bra.uni D%=;\n\t"                                             \
            "bra.uni W%=;\n\t"                                                 \
            "D%=:\n\t}" :: "r"(_m), "r"(_p) : "memory");                       \
    }                                                                          \
} while (0)

__device__ __forceinline__ void bulk_g2s(uint32_t dst, const void* src, uint32_t bytes, uint32_t mbar) {
    asm volatile("cp.async.bulk.shared::cta.global.mbarrier::complete_tx::bytes [%0], [%1], %2, [%3];"
        :: "r"(dst), "l"(src), "r"(bytes), "r"(mbar) : "memory");
}

__device__ __forceinline__ void ldsm4(uint32_t* d, uint32_t addr) {
    asm volatile("ldmatrix.sync.aligned.m8n8.x4.shared.b16 {%0,%1,%2,%3}, [%4];"
        : "=r"(d[0]), "=r"(d[1]), "=r"(d[2]), "=r"(d[3]) : "r"(addr));
}
__device__ __forceinline__ void ldsm2(uint32_t* d, uint32_t addr) {
    asm volatile("ldmatrix.sync.aligned.m8n8.x2.shared.b16 {%0,%1}, [%2];"
        : "=r"(d[0]), "=r"(d[1]) : "r"(addr));
}
__device__ __forceinline__ void mma16816(float* c, const uint32_t* a, const uint32_t* b) {
    asm volatile("mma.sync.aligned.m16n8k16.row.col.f32.bf16.bf16.f32 "
        "{%0,%1,%2,%3}, {%4,%5,%6,%7}, {%8,%9}, {%0,%1,%2,%3};"
        : "+f"(c[0]), "+f"(c[1]), "+f"(c[2]), "+f"(c[3])
        : "r"(a[0]), "r"(a[1]), "r"(a[2]), "r"(a[3]), "r"(b[0]), "r"(b[1]));
}

// ---------------------------------------------------------------------------
// Prep: W1eff[k][n] = conv folded into w1; transposed [n][k] rows, bf16 hi
// (truncation) + bf16 lo (rn of residual), 144B row stride, per-chunk images.
// ---------------------------------------------------------------------------
__global__ void prep_kernel(const float* __restrict__ conv_w, const float* __restrict__ w1) {
    int p = blockIdx.x;    // k: 0..831
    int h = threadIdx.x;   // n: 0..207
    float s = 0.f;
    if (p < KTOT && h < NHID) {
        int y = p / 28, xx = p % 28;
#pragma unroll
        for (int di = 0; di < 3; ++di) {
            int oy = y - di;
            if (oy < 0 || oy > 25) continue;
#pragma unroll
            for (int dj = 0; dj < 3; ++dj) {
                int ox = xx - dj;
                if (ox < 0 || ox > 25) continue;
                s += conv_w[di * 3 + dj] * w1[(oy * 26 + ox) * NHID + h];
            }
        }
    }
    uint32_t sbits = __float_as_uint(s);
    uint32_t hib = sbits & 0xFFFF0000u;
    float r = s - __uint_as_float(hib);
    __nv_bfloat16 lo16 = __float2bfloat16(r);
    unsigned short lo_us = *reinterpret_cast<unsigned short*>(&lo16);

    int chunk = p >> 6, kl = p & 63;
    size_t off = (size_t)chunk * BCH + (size_t)h * ROWB + (size_t)kl * 2;
    *(unsigned short*)(g_wB_hi + off) = (unsigned short)(hib >> 16);
    *(unsigned short*)(g_wB_lo + off) = lo_us;
}

// Split 8 fp32 into bf16-hi (trunc) + bf16-lo (rn residual), packed pairs.
__device__ __forceinline__ void split8(float4 v0, float4 v1, uint4& hi, uint4& lo) {
    uint32_t a[8] = {__float_as_uint(v0.x), __float_as_uint(v0.y), __float_as_uint(v0.z), __float_as_uint(v0.w),
                     __float_as_uint(v1.x), __float_as_uint(v1.y), __float_as_uint(v1.z), __float_as_uint(v1.w)};
    uint32_t rb[8];
#pragma unroll
    for (int i = 0; i < 8; ++i) {
        float t = __uint_as_float(a[i] & 0xFFFF0000u);
        float res = __uint_as_float(a[i]) - t;
        __nv_bfloat16 lb = __float2bfloat16(res);
        rb[i] = (uint32_t)(*reinterpret_cast<unsigned short*>(&lb)) << 16;
    }
    hi.x = __byte_perm(a[0], a[1], 0x7632); hi.y = __byte_perm(a[2], a[3], 0x7632);
    hi.z = __byte_perm(a[4], a[5], 0x7632); hi.w = __byte_perm(a[6], a[7], 0x7632);
    lo.x = __byte_perm(rb[0], rb[1], 0x7632); lo.y = __byte_perm(rb[2], rb[3], 0x7632);
    lo.z = __byte_perm(rb[4], rb[5], 0x7632); lo.w = __byte_perm(rb[6], rb[7], 0x7632);
}

// One k16-step of the warp tile: 3 split-bf16 terms, 39 MMAs.
__device__ __forceinline__ void kstep(uint32_t aHiB, uint32_t aLoB,
                                      uint32_t bHiB, uint32_t bLoB,
                                      uint32_t kb, float* acc) {
    uint32_t bf[26], ah[4], al[4];
#pragma unroll
    for (int tp = 0; tp < 6; ++tp) ldsm4(&bf[tp * 4], bHiB + tp * (16 * ROWB) + kb);
    ldsm2(&bf[24], bHiB + 6 * (16 * ROWB) + kb);
    ldsm4(ah, aHiB + kb);
    ldsm4(al, aLoB + kb);
#pragma unroll
    for (int tn = 0; tn < 13; ++tn) mma16816(&acc[tn * 4], ah, &bf[tn * 2]);
#pragma unroll
    for (int tn = 0; tn < 13; ++tn) mma16816(&acc[tn * 4], al, &bf[tn * 2]);
#pragma unroll
    for (int tp = 0; tp < 6; ++tp) ldsm4(&bf[tp * 4], bLoB + tp * (16 * ROWB) + kb);
    ldsm2(&bf[24], bLoB + 6 * (16 * ROWB) + kb);
#pragma unroll
    for (int tn = 0; tn < 13; ++tn) mma16816(&acc[tn * 4], ah, &bf[tn * 2]);
}

// ---------------------------------------------------------------------------
// Fused: out = relu(X @ W1eff + b1) @ w2 + b2  (split-bf16 mma.sync)
// 16 warps = 8m x 2n; warp tile 16(m) x 104(n). Global x loads for chunk i+1
// issued before the MMA burst of chunk i; convert/store after (latency hidden).
// ---------------------------------------------------------------------------
__global__ __launch_bounds__(NTHREADS, 1)
void fused_mma_kernel(const float* __restrict__ x,
                      const float* __restrict__ b1,
                      const float* __restrict__ w2,
                      const float* __restrict__ b2,
                      float* __restrict__ out) {
    extern __shared__ __align__(1024) unsigned char smem[];
    const uint32_t sb = smem_u32(smem);
    const int tid  = threadIdx.x;
    const int wid  = tid >> 5;
    const int lane = tid & 31;
    const int m0   = blockIdx.x * BM;

    // this thread's two A-granules (m row, k-octet) within a chunk
    const int g_m0 = tid >> 3,          g_g0 = tid & 7;
    const int g_m1 = (tid + 512) >> 3,  g_g1 = tid & 7;

    float* w2s = (float*)(smem + SM_W2);
    float* b1s = (float*)(smem + SM_B1);
    float* b2s = (float*)(smem + SM_B2);

    if (tid == 0) {
        MBARRIER_INIT(sb + SM_MB0, 1);
        MBARRIER_INIT(sb + SM_MB1, 1);
    }
    for (int e = tid; e < NHID * NCLS; e += NTHREADS) w2s[e] = w2[e];
    for (int e = tid; e < NHID; e += NTHREADS)        b1s[e] = b1[e];
    if (tid < NCLS)                                   b2s[tid] = b2[tid];
    __syncthreads();

    const int lg = lane >> 3, lr = lane & 7;
    const uint32_t a_off = (uint32_t)(((lg & 1) * 8 + lr) * ROWB + (lg >> 1) * 16);
    const uint32_t b_off = (uint32_t)(((lg >> 1) * 8 + lr) * ROWB + (lg & 1) * 16);
    const int wm = (wid >> 1) * 16;
    const int wn = (wid & 1) * 104;

    float acc[52];
#pragma unroll
    for (int i = 0; i < 52; ++i) acc[i] = 0.f;

    // ---------------- prologue: B(0) in flight, A(0) converted ----------------
    if (tid == 0) {
        MBARRIER_EXPECT_TX(sb + SM_MB0, 2 * BCH);
        bulk_g2s(sb + SM_B(0, 0), g_wB_hi, BCH, sb + SM_MB0);
        bulk_g2s(sb + SM_B(0, 1), g_wB_lo, BCH, sb + SM_MB0);
    }
    {
        unsigned char* Ahi = smem + SM_A(0, 0);
        unsigned char* Alo = smem + SM_A(0, 1);
        float4 v0a = ((const float4*)(x + (size_t)(m0 + g_m0) * KTOT + g_g0 * 8))[0];
        float4 v0b = ((const float4*)(x + (size_t)(m0 + g_m0) * KTOT + g_g0 * 8))[1];
        float4 v1a = ((const float4*)(x + (size_t)(m0 + g_m1) * KTOT + g_g1 * 8))[0];
        float4 v1b = ((const float4*)(x + (size_t)(m0 + g_m1) * KTOT + g_g1 * 8))[1];
        uint4 hi, lo;
        split8(v0a, v0b, hi, lo);
        uint32_t so0 = (uint32_t)g_m0 * ROWB + (uint32_t)g_g0 * 16;
        *(uint4*)(Ahi + so0) = hi; *(uint4*)(Alo + so0) = lo;
        split8(v1a, v1b, hi, lo);
        uint32_t so1 = (uint32_t)g_m1 * ROWB + (uint32_t)g_g1 * 16;
        *(uint4*)(Ahi + so1) = hi; *(uint4*)(Alo + so1) = lo;
    }
    __syncthreads();

    // ---------------- main loop ----------------
#pragma unroll 1
    for (int i = 0; i < NCHUNK; ++i) {
        const int s = i & 1;
        const bool hasNext = (i + 1 < NCHUNK);

        // issue B(i+1) into the other buffer (freed by last iteration's sync)
        if (hasNext && tid == 0) {
            const uint32_t mb = sb + (s ? SM_MB0 : SM_MB1);
            MBARRIER_EXPECT_TX(mb, 2 * BCH);
            bulk_g2s(sb + SM_B(1 - s, 0), g_wB_hi + (size_t)(i + 1) * BCH, BCH, mb);
            bulk_g2s(sb + SM_B(1 - s, 1), g_wB_lo + (size_t)(i + 1) * BCH, BCH, mb);
        }

        // issue global x loads for chunk i+1 (latency hidden behind MMAs)
        float4 p0a, p0b, p1a, p1b;
        bool val0 = false, val1 = false;
        if (hasNext) {
            const int k0n = (i + 1) * BK;
            const int kg0 = k0n + g_g0 * 8;
            const int kg1 = k0n + g_g1 * 8;
            val0 = kg0 < KTOT;
            val1 = kg1 < KTOT;
            if (val0) {
                const float4* src = (const float4*)(x + (size_t)(m0 + g_m0) * KTOT + kg0);
                p0a = src[0]; p0b = src[1];
            }
            if (val1) {
                const float4* src = (const float4*)(x + (size_t)(m0 + g_m1) * KTOT + kg1);
                p1a = src[0]; p1b = src[1];
            }
        }

        // wait for B(i)
        MBARRIER_WAIT_PARITY(sb + (s ? SM_MB1 : SM_MB0), (i >> 1) & 1);

        const uint32_t aHiB = sb + SM_A(s, 0) + (uint32_t)wm * ROWB + a_off;
        const uint32_t aLoB = sb + SM_A(s, 1) + (uint32_t)wm * ROWB + a_off;
        const uint32_t bHiB = sb + SM_B(s, 0) + (uint32_t)wn * ROWB + b_off;
        const uint32_t bLoB = sb + SM_B(s, 1) + (uint32_t)wn * ROWB + b_off;

        if (i != NCHUNK - 1) {
            kstep(aHiB, aLoB, bHiB, bLoB, 0,  acc);
            kstep(aHiB, aLoB, bHiB, bLoB, 32, acc);
            kstep(aHiB, aLoB, bHiB, bLoB, 64, acc);
            kstep(aHiB, aLoB, bHiB, bLoB, 96, acc);
        } else {
            kstep(aHiB, aLoB, bHiB, bLoB, 0, acc);   // 784 = 12*64 + 16
        }

        // convert + store A(i+1) into the other stage
        if (hasNext) {
            unsigned char* Ahi = smem + SM_A(1 - s, 0);
            unsigned char* Alo = smem + SM_A(1 - s, 1);
            uint4 hi = {0,0,0,0}, lo = {0,0,0,0};
            if (val0) split8(p0a, p0b, hi, lo);
            uint32_t so0 = (uint32_t)g_m0 * ROWB + (uint32_t)g_g0 * 16;
            *(uint4*)(Ahi + so0) = hi; *(uint4*)(Alo + so0) = lo;
            uint4 hi1 = {0,0,0,0}, lo1 = {0,0,0,0};
            if (val1) split8(p1a, p1b, hi1, lo1);
            uint32_t so1 = (uint32_t)g_m1 * ROWB + (uint32_t)g_g1 * 16;
            *(uint4*)(Ahi + so1) = hi1; *(uint4*)(Alo + so1) = lo1;
        }
        __syncthreads();
    }

    // ---------------- epilogue: relu(+b1) -> smem, then @ w2 + b2 ----------------
    float* hid  = (float*)(smem + SM_HID);    // [128][210]
    float* outp = (float*)(smem + SM_OUTP);   // [128][10]

#pragma unroll
    for (int tn = 0; tn < 13; ++tn) {
        int c = wn + tn * 8 + (lane & 3) * 2;
        if (c < NHID) {
            int r0 = wm + (lane >> 2);
            float b1a = b1s[c], b1b = b1s[c + 1];
            const float* a = &acc[tn * 4];
            hid[r0 * HSTRIDE + c]           = fmaxf(a[0] + b1a, 0.f);
            hid[r0 * HSTRIDE + c + 1]       = fmaxf(a[1] + b1b, 0.f);
            hid[(r0 + 8) * HSTRIDE + c]     = fmaxf(a[2] + b1a, 0.f);
            hid[(r0 + 8) * HSTRIDE + c + 1] = fmaxf(a[3] + b1b, 0.f);
        }
    }
    for (int e = tid; e < BM * NCLS; e += NTHREADS) outp[e] = 0.f;
    __syncthreads();

    {
        int m  = tid >> 2;                  // 0..127
        int h0 = (tid & 3) * 50;            // 4 k-slices of 50
        float p[NCLS];
#pragma unroll
        for (int c = 0; c < NCLS; ++c) p[c] = 0.f;
        for (int h = h0; h < h0 + 50; ++h) {
            float v = hid[m * HSTRIDE + h];
#pragma unroll
            for (int c = 0; c < NCLS; ++c) p[c] += v * w2s[h * NCLS + c];
        }
#pragma unroll
        for (int c = 0; c < NCLS; ++c) atomicAdd(&outp[m * NCLS + c], p[c]);
    }
    __syncthreads();

    for (int e = tid; e < BM * NCLS; e += NTHREADS)
        out[(size_t)m0 * NCLS + e] = outp[e] + b2s[e % NCLS];
}

// ---------------------------------------------------------------------------
extern "C" void kernel_launch(void* const* d_in, const int* in_sizes, int n_in,
                              void* d_out, int out_size) {
    const float* x      = (const float*)d_in[0];   // [65536, 784]
    const float* conv_w = (const float*)d_in[1];   // [3, 3]
    const float* w1     = (const float*)d_in[2];   // [676, 200]
    const float* b1     = (const float*)d_in[3];   // [200]
    const float* w2     = (const float*)d_in[4];   // [200, 10]
    const float* b2     = (const float*)d_in[5];   // [10]
    float* out          = (float*)d_out;           // [65536, 10]

    cudaFuncSetAttribute(fused_mma_kernel,
                         cudaFuncAttributeMaxDynamicSharedMemorySize, SMEM_TOTAL);

    prep_kernel<<<NCHUNK * BK, NPAD>>>(conv_w, w1);
    fused_mma_kernel<<<65536 / BM, NTHREADS, SMEM_TOTAL>>>(x, b1, w2, b2, out);
}

// round 7
// speedup vs baseline: 1.9458x; 1.4295x over previous
#include <cuda_runtime.h>
#include <cuda_fp16.h>
#include <cstdint>

// ---------------- problem constants ----------------
#define KTOT 784            // 28*28 GEMM K
#define NHID 200            // hidden width
#define NPAD 208            // N padded to 26*8
#define NCLS 10
#define BM   128            // rows per CTA
#define BK   64             // K per chunk
#define NCHUNK 13           // 12*64 + 16 (last chunk: 1 k-step)
#define ROWB 144            // bytes per fp16 row -> LDSM conflict-free
#define ACH  (BM * ROWB)    // 18432 per term
#define BCH  (NPAD * ROWB)  // 29952
#define NTHREADS 512

// ---------------- smem layout (bytes) ----------------
#define SM_MB0   0
#define SM_MB1   8
#define SM_W2    64                         // 2000 floats
#define SM_B1    8064                       // 200 floats
#define SM_B2    8864                       // 10 floats
#define SM_ABASE 9216
#define SM_A(s, t) (SM_ABASE + ((s) * 2 + (t)) * ACH)          // 4 x 18432
#define SM_BBASE (SM_ABASE + 4 * ACH)                          // 82944
#define SM_B(s)  (SM_BBASE + (s) * BCH)                        // 2 x 29952
#define SMEM_TOTAL (SM_BBASE + 2 * BCH)                        // 142848
// epilogue reuse
#define SM_HID   9216                       // 128 x 210 floats
#define HSTRIDE  210
#define SM_OUTP  (SM_HID + BM * HSTRIDE * 4)

// Per-chunk images of W1eff^T (n-major rows, 144B stride) in fp16.
__device__ __align__(16) unsigned char g_wB[NCHUNK * BCH];

// ---------------- PTX helpers ----------------
__device__ __forceinline__ uint32_t smem_u32(const void* p) {
    uint32_t a;
    asm("{ .reg .u64 t; cvta.to.shared.u64 t, %1; cvt.u32.u64 %0, t; }" : "=r"(a) : "l"(p));
    return a;
}

#define MBARRIER_INIT(a, n) \
    asm volatile("mbarrier.init.shared.b64 [%0], %1;" :: "r"(a), "r"((uint32_t)(n)) : "memory")
#define MBARRIER_EXPECT_TX(a, b) \
    asm volatile("mbarrier.arrive.expect_tx.shared.b64 _, [%0], %1;" :: "r"(a), "r"((uint32_t)(b)) : "memory")

#define MBARRIER_WAIT_PARITY(mbar, par) do {                                   \
    uint32_t _m = (mbar), _p = (par), _d;                                      \
    asm volatile("{\n\t.reg .pred p;\n\t"                                      \
        "mbarrier.try_wait.parity.acquire.cta.shared::cta.b64 p, [%1], %2;\n\t"\
        "selp.b32 %0, 1, 0, p;\n\t}"                                           \
        : "=r"(_d) : "r"(_m), "r"(_p) : "memory");                             \
    if (!_d) {                                                                 \
        asm volatile("{\n\t.reg .pred P1;\n\t"                                 \
            "W%=:\n\t"                                                         \
            "mbarrier.try_wait.parity.acquire.cta.shared::cta.b64 P1, [%0], %1, 0x989680;\n\t" \
            "@P1 bra.uni D%=;\n\t"                                             \
            "bra.uni W%=;\n\t"                                                 \
            "D%=:\n\t}" :: "r"(_m), "r"(_p) : "memory");                       \
    }                                                                          \
} while (0)

__device__ __forceinline__ void bulk_g2s(uint32_t dst, const void* src, uint32_t bytes, uint32_t mbar) {
    asm volatile("cp.async.bulk.shared::cta.global.mbarrier::complete_tx::bytes [%0], [%1], %2, [%3];"
        :: "r"(dst), "l"(src), "r"(bytes), "r"(mbar) : "memory");
}

__device__ __forceinline__ void ldsm4(uint32_t* d, uint32_t addr) {
    asm volatile("ldmatrix.sync.aligned.m8n8.x4.shared.b16 {%0,%1,%2,%3}, [%4];"
        : "=r"(d[0]), "=r"(d[1]), "=r"(d[2]), "=r"(d[3]) : "r"(addr));
}
__device__ __forceinline__ void ldsm2(uint32_t* d, uint32_t addr) {
    asm volatile("ldmatrix.sync.aligned.m8n8.x2.shared.b16 {%0,%1}, [%2];"
        : "=r"(d[0]), "=r"(d[1]) : "r"(addr));
}
__device__ __forceinline__ void mma16816(float* c, const uint32_t* a, const uint32_t* b) {
    asm volatile("mma.sync.aligned.m16n8k16.row.col.f32.f16.f16.f32 "
        "{%0,%1,%2,%3}, {%4,%5,%6,%7}, {%8,%9}, {%0,%1,%2,%3};"
        : "+f"(c[0]), "+f"(c[1]), "+f"(c[2]), "+f"(c[3])
        : "r"(a[0]), "r"(a[1]), "r"(a[2]), "r"(a[3]), "r"(b[0]), "r"(b[1]));
}

// ---------------------------------------------------------------------------
// Prep: W1eff[k][n] = conv folded into w1; transposed [n][k] rows, fp16 rn,
// 144B row stride, per-chunk images ready for cp.async.bulk.
// ---------------------------------------------------------------------------
__global__ void prep_kernel(const float* __restrict__ conv_w, const float* __restrict__ w1) {
    int p = blockIdx.x;    // k: 0..831
    int h = threadIdx.x;   // n: 0..207
    float s = 0.f;
    if (p < KTOT && h < NHID) {
        int y = p / 28, xx = p % 28;
#pragma unroll
        for (int di = 0; di < 3; ++di) {
            int oy = y - di;
            if (oy < 0 || oy > 25) continue;
#pragma unroll
            for (int dj = 0; dj < 3; ++dj) {
                int ox = xx - dj;
                if (ox < 0 || ox > 25) continue;
                s += conv_w[di * 3 + dj] * w1[(oy * 26 + ox) * NHID + h];
            }
        }
    }
    __half hv = __float2half_rn(s);
    int chunk = p >> 6, kl = p & 63;
    size_t off = (size_t)chunk * BCH + (size_t)h * ROWB + (size_t)kl * 2;
    *(unsigned short*)(g_wB + off) = __half_as_ushort(hv);
}

// Split 8 fp32 into fp16-hi (rn) + fp16-lo (rn of residual), packed pairs.
__device__ __forceinline__ void split8(float4 v0, float4 v1, uint4& hi, uint4& lo) {
    float a[8] = {v0.x, v0.y, v0.z, v0.w, v1.x, v1.y, v1.z, v1.w};
    uint32_t hp[4], lp[4];
#pragma unroll
    for (int i = 0; i < 4; ++i) {
        __half2 h2 = __floats2half2_rn(a[i * 2], a[i * 2 + 1]);
        hp[i] = *reinterpret_cast<uint32_t*>(&h2);
        float r0 = a[i * 2]     - __low2float(h2);
        float r1 = a[i * 2 + 1] - __high2float(h2);
        __half2 l2 = __floats2half2_rn(r0, r1);
        lp[i] = *reinterpret_cast<uint32_t*>(&l2);
    }
    hi.x = hp[0]; hi.y = hp[1]; hi.z = hp[2]; hi.w = hp[3];
    lo.x = lp[0]; lo.y = lp[1]; lo.z = lp[2]; lo.w = lp[3];
}

// One k16-step of the warp tile: 2 split-fp16 terms, 26 MMAs, one B load.
__device__ __forceinline__ void kstep(uint32_t aHiB, uint32_t aLoB, uint32_t bB,
                                      uint32_t kb, float* acc) {
    uint32_t bf[26], ah[4], al[4];
#pragma unroll
    for (int tp = 0; tp < 6; ++tp) ldsm4(&bf[tp * 4], bB + tp * (16 * ROWB) + kb);
    ldsm2(&bf[24], bB + 6 * (16 * ROWB) + kb);
    ldsm4(ah, aHiB + kb);
    ldsm4(al, aLoB + kb);
#pragma unroll
    for (int tn = 0; tn < 13; ++tn) mma16816(&acc[tn * 4], ah, &bf[tn * 2]);
#pragma unroll
    for (int tn = 0; tn < 13; ++tn) mma16816(&acc[tn * 4], al, &bf[tn * 2]);
}

// ---------------------------------------------------------------------------
// Fused: out = relu(X @ W1eff + b1) @ w2 + b2  (split-fp16 mma.sync, 2 terms)
// 16 warps = 8m x 2n; warp tile 16(m) x 104(n). Global x loads for chunk i+1
// issued before the MMA burst of chunk i; convert/store after (latency hidden).
// ---------------------------------------------------------------------------
__global__ __launch_bounds__(NTHREADS, 1)
void fused_mma_kernel(const float* __restrict__ x,
                      const float* __restrict__ b1,
                      const float* __restrict__ w2,
                      const float* __restrict__ b2,
                      float* __restrict__ out) {
    extern __shared__ __align__(1024) unsigned char smem[];
    const uint32_t sb = smem_u32(smem);
    const int tid  = threadIdx.x;
    const int wid  = tid >> 5;
    const int lane = tid & 31;
    const int m0   = blockIdx.x * BM;

    // this thread's two A-granules (m row, k-octet) within a chunk
    const int g_m0 = tid >> 3,          g_g0 = tid & 7;
    const int g_m1 = (tid + 512) >> 3,  g_g1 = tid & 7;

    float* w2s = (float*)(smem + SM_W2);
    float* b1s = (float*)(smem + SM_B1);
    float* b2s = (float*)(smem + SM_B2);

    if (tid == 0) {
        MBARRIER_INIT(sb + SM_MB0, 1);
        MBARRIER_INIT(sb + SM_MB1, 1);
    }
    for (int e = tid; e < NHID * NCLS; e += NTHREADS) w2s[e] = w2[e];
    for (int e = tid; e < NHID; e += NTHREADS)        b1s[e] = b1[e];
    if (tid < NCLS)                                   b2s[tid] = b2[tid];
    __syncthreads();

    const int lg = lane >> 3, lr = lane & 7;
    const uint32_t a_off = (uint32_t)(((lg & 1) * 8 + lr) * ROWB + (lg >> 1) * 16);
    const uint32_t b_off = (uint32_t)(((lg >> 1) * 8 + lr) * ROWB + (lg & 1) * 16);
    const int wm = (wid >> 1) * 16;
    const int wn = (wid & 1) * 104;

    float acc[52];
#pragma unroll
    for (int i = 0; i < 52; ++i) acc[i] = 0.f;

    // ---------------- prologue: B(0) in flight, A(0) converted ----------------
    if (tid == 0) {
        MBARRIER_EXPECT_TX(sb + SM_MB0, BCH);
        bulk_g2s(sb + SM_B(0), g_wB, BCH, sb + SM_MB0);
    }
    {
        unsigned char* Ahi = smem + SM_A(0, 0);
        unsigned char* Alo = smem + SM_A(0, 1);
        float4 v0a = ((const float4*)(x + (size_t)(m0 + g_m0) * KTOT + g_g0 * 8))[0];
        float4 v0b = ((const float4*)(x + (size_t)(m0 + g_m0) * KTOT + g_g0 * 8))[1];
        float4 v1a = ((const float4*)(x + (size_t)(m0 + g_m1) * KTOT + g_g1 * 8))[0];
        float4 v1b = ((const float4*)(x + (size_t)(m0 + g_m1) * KTOT + g_g1 * 8))[1];
        uint4 hi, lo;
        split8(v0a, v0b, hi, lo);
        uint32_t so0 = (uint32_t)g_m0 * ROWB + (uint32_t)g_g0 * 16;
        *(uint4*)(Ahi + so0) = hi; *(uint4*)(Alo + so0) = lo;
        split8(v1a, v1b, hi, lo);
        uint32_t so1 = (uint32_t)g_m1 * ROWB + (uint32_t)g_g1 * 16;
        *(uint4*)(Ahi + so1) = hi; *(uint4*)(Alo + so1) = lo;
    }
    __syncthreads();

    // ---------------- main loop ----------------
#pragma unroll 1
    for (int i = 0; i < NCHUNK; ++i) {
        const int s = i & 1;
        const bool hasNext = (i + 1 < NCHUNK);

        // issue B(i+1) into the other buffer (freed by last iteration's sync)
        if (hasNext && tid == 0) {
            const uint32_t mb = sb + (s ? SM_MB0 : SM_MB1);
            MBARRIER_EXPECT_TX(mb, BCH);
            bulk_g2s(sb + SM_B(1 - s), g_wB + (size_t)(i + 1) * BCH, BCH, mb);
        }

        // issue global x loads for chunk i+1 (latency hidden behind MMAs)
        float4 p0a, p0b, p1a, p1b;
        bool val0 = false, val1 = false;
        if (hasNext) {
            const int k0n = (i + 1) * BK;
            const int kg0 = k0n + g_g0 * 8;
            const int kg1 = k0n + g_g1 * 8;
            val0 = kg0 < KTOT;
            val1 = kg1 < KTOT;
            if (val0) {
                const float4* src = (const float4*)(x + (size_t)(m0 + g_m0) * KTOT + kg0);
                p0a = src[0]; p0b = src[1];
            }
            if (val1) {
                const float4* src = (const float4*)(x + (size_t)(m0 + g_m1) * KTOT + kg1);
                p1a = src[0]; p1b = src[1];
            }
        }

        // wait for B(i)
        MBARRIER_WAIT_PARITY(sb + (s ? SM_MB1 : SM_MB0), (i >> 1) & 1);

        const uint32_t aHiB = sb + SM_A(s, 0) + (uint32_t)wm * ROWB + a_off;
        const uint32_t aLoB = sb + SM_A(s, 1) + (uint32_t)wm * ROWB + a_off;
        const uint32_t bB   = sb + SM_B(s)    + (uint32_t)wn * ROWB + b_off;

        if (i != NCHUNK - 1) {
            kstep(aHiB, aLoB, bB, 0,  acc);
            kstep(aHiB, aLoB, bB, 32, acc);
            kstep(aHiB, aLoB, bB, 64, acc);
            kstep(aHiB, aLoB, bB, 96, acc);
        } else {
            kstep(aHiB, aLoB, bB, 0, acc);   // 784 = 12*64 + 16
        }

        // convert + store A(i+1) into the other stage
        if (hasNext) {
            unsigned char* Ahi = smem + SM_A(1 - s, 0);
            unsigned char* Alo = smem + SM_A(1 - s, 1);
            uint4 hi = {0,0,0,0}, lo = {0,0,0,0};
            if (val0) split8(p0a, p0b, hi, lo);
            uint32_t so0 = (uint32_t)g_m0 * ROWB + (uint32_t)g_g0 * 16;
            *(uint4*)(Ahi + so0) = hi; *(uint4*)(Alo + so0) = lo;
            uint4 hi1 = {0,0,0,0}, lo1 = {0,0,0,0};
            if (val1) split8(p1a, p1b, hi1, lo1);
            uint32_t so1 = (uint32_t)g_m1 * ROWB + (uint32_t)g_g1 * 16;
            *(uint4*)(Ahi + so1) = hi1; *(uint4*)(Alo + so1) = lo1;
        }
        __syncthreads();
    }

    // ---------------- epilogue: relu(+b1) -> smem, then @ w2 + b2 ----------------
    float* hid  = (float*)(smem + SM_HID);    // [128][210]
    float* outp = (float*)(smem + SM_OUTP);   // [128][10]

#pragma unroll
    for (int tn = 0; tn < 13; ++tn) {
        int c = wn + tn * 8 + (lane & 3) * 2;
        if (c < NHID) {
            int r0 = wm + (lane >> 2);
            float b1a = b1s[c], b1b = b1s[c + 1];
            const float* a = &acc[tn * 4];
            hid[r0 * HSTRIDE + c]           = fmaxf(a[0] + b1a, 0.f);
            hid[r0 * HSTRIDE + c + 1]       = fmaxf(a[1] + b1b, 0.f);
            hid[(r0 + 8) * HSTRIDE + c]     = fmaxf(a[2] + b1a, 0.f);
            hid[(r0 + 8) * HSTRIDE + c + 1] = fmaxf(a[3] + b1b, 0.f);
        }
    }
    for (int e = tid; e < BM * NCLS; e += NTHREADS) outp[e] = 0.f;
    __syncthreads();

    {
        int m  = tid >> 2;                  // 0..127
        int h0 = (tid & 3) * 50;            // 4 k-slices of 50
        float p[NCLS];
#pragma unroll
        for (int c = 0; c < NCLS; ++c) p[c] = 0.f;
        for (int h = h0; h < h0 + 50; ++h) {
            float v = hid[m * HSTRIDE + h];
#pragma unroll
            for (int c = 0; c < NCLS; ++c) p[c] += v * w2s[h * NCLS + c];
        }
#pragma unroll
        for (int c = 0; c < NCLS; ++c) atomicAdd(&outp[m * NCLS + c], p[c]);
    }
    __syncthreads();

    for (int e = tid; e < BM * NCLS; e += NTHREADS)
        out[(size_t)m0 * NCLS + e] = outp[e] + b2s[e % NCLS];
}

// ---------------------------------------------------------------------------
extern "C" void kernel_launch(void* const* d_in, const int* in_sizes, int n_in,
                              void* d_out, int out_size) {
    const float* x      = (const float*)d_in[0];   // [65536, 784]
    const float* conv_w = (const float*)d_in[1];   // [3, 3]
    const float* w1     = (const float*)d_in[2];   // [676, 200]
    const float* b1     = (const float*)d_in[3];   // [200]
    const float* w2     = (const float*)d_in[4];   // [200, 10]
    const float* b2     = (const float*)d_in[5];   // [10]
    float* out          = (float*)d_out;           // [65536, 10]

    cudaFuncSetAttribute(fused_mma_kernel,
                         cudaFuncAttributeMaxDynamicSharedMemorySize, SMEM_TOTAL);

    prep_kernel<<<NCHUNK * BK, NPAD>>>(conv_w, w1);
    fused_mma_kernel<<<65536 / BM, NTHREADS, SMEM_TOTAL>>>(x, b1, w2, b2, out);
}

// round 8
// speedup vs baseline: 2.5726x; 1.3221x over previous
#include <cuda_runtime.h>
#include <cuda_fp16.h>
#include <cstdint>

// ---------------- problem constants ----------------
#define KTOT 784            // 28*28 GEMM K
#define NHID 200            // hidden width
#define NPAD 224            // N padded to 28*8 (4 n-warps x 56)
#define NCLS 10
#define BM   128            // rows per CTA
#define BK   64             // K per chunk
#define NCHUNK 13           // 12*64 + 16 (last chunk: 1 k-step)
#define ROWB 144            // bytes per fp16 row -> LDSM conflict-free
#define ACH  (BM * ROWB)    // 18432
#define BCH  (NPAD * ROWB)  // 32256
#define NTHREADS 512

// ---------------- smem layout (bytes) ----------------
#define SM_MB0   0
#define SM_MB1   8
#define SM_W2    64                         // 2000 floats
#define SM_B1    8064                       // 200 floats
#define SM_B2    8864                       // 10 floats
#define SM_ABASE 9216
#define SM_A(s)  (SM_ABASE + (s) * ACH)                        // 2 x 18432
#define SM_BBASE (SM_ABASE + 2 * ACH)                          // 46080
#define SM_B(s)  (SM_BBASE + (s) * BCH)                        // 2 x 32256
// epilogue reuse
#define SM_HID   9216                       // 128 x 210 floats
#define HSTRIDE  210
#define SM_OUTP  (SM_HID + BM * HSTRIDE * 4)                   // 116736
#define SMEM_TOTAL (SM_OUTP + BM * NCLS * 4)                   // 121856

// Per-chunk images of W1eff^T (n-major rows, 144B stride) in fp16.
__device__ __align__(16) unsigned char g_wB[NCHUNK * BCH];

// ---------------- PTX helpers ----------------
__device__ __forceinline__ uint32_t smem_u32(const void* p) {
    uint32_t a;
    asm("{ .reg .u64 t; cvta.to.shared.u64 t, %1; cvt.u32.u64 %0, t; }" : "=r"(a) : "l"(p));
    return a;
}

#define MBARRIER_INIT(a, n) \
    asm volatile("mbarrier.init.shared.b64 [%0], %1;" :: "r"(a), "r"((uint32_t)(n)) : "memory")
#define MBARRIER_EXPECT_TX(a, b) \
    asm volatile("mbarrier.arrive.expect_tx.shared.b64 _, [%0], %1;" :: "r"(a), "r"((uint32_t)(b)) : "memory")

#define MBARRIER_WAIT_PARITY(mbar, par) do {                                   \
    uint32_t _m = (mbar), _p = (par), _d;                                      \
    asm volatile("{\n\t.reg .pred p;\n\t"                                      \
        "mbarrier.try_wait.parity.acquire.cta.shared::cta.b64 p, [%1], %2;\n\t"\
        "selp.b32 %0, 1, 0, p;\n\t}"                                           \
        : "=r"(_d) : "r"(_m), "r"(_p) : "memory");                             \
    if (!_d) {                                                                 \
        asm volatile("{\n\t.reg .pred P1;\n\t"                                 \
            "W%=:\n\t"                                                         \
            "mbarrier.try_wait.parity.acquire.cta.shared::cta.b64 P1, [%0], %1, 0x989680;\n\t" \
            "@P1 bra.uni D%=;\n\t"                                             \
            "bra.uni W%=;\n\t"                                                 \
            "D%=:\n\t}" :: "r"(_m), "r"(_p) : "memory");                       \
    }                                                                          \
} while (0)

__device__ __forceinline__ void bulk_g2s(uint32_t dst, const void* src, uint32_t bytes, uint32_t mbar) {
    asm volatile("cp.async.bulk.shared::cta.global.mbarrier::complete_tx::bytes [%0], [%1], %2, [%3];"
        :: "r"(dst), "l"(src), "r"(bytes), "r"(mbar) : "memory");
}

__device__ __forceinline__ void ldsm4(uint32_t* d, uint32_t addr) {
    asm volatile("ldmatrix.sync.aligned.m8n8.x4.shared.b16 {%0,%1,%2,%3}, [%4];"
        : "=r"(d[0]), "=r"(d[1]), "=r"(d[2]), "=r"(d[3]) : "r"(addr));
}
__device__ __forceinline__ void ldsm2(uint32_t* d, uint32_t addr) {
    asm volatile("ldmatrix.sync.aligned.m8n8.x2.shared.b16 {%0,%1}, [%2];"
        : "=r"(d[0]), "=r"(d[1]) : "r"(addr));
}
__device__ __forceinline__ void mma16816(float* c, const uint32_t* a, const uint32_t* b) {
    asm volatile("mma.sync.aligned.m16n8k16.row.col.f32.f16.f16.f32 "
        "{%0,%1,%2,%3}, {%4,%5,%6,%7}, {%8,%9}, {%0,%1,%2,%3};"
        : "+f"(c[0]), "+f"(c[1]), "+f"(c[2]), "+f"(c[3])
        : "r"(a[0]), "r"(a[1]), "r"(a[2]), "r"(a[3]), "r"(b[0]), "r"(b[1]));
}

// ---------------------------------------------------------------------------
// Prep: W1eff[k][n] = conv folded into w1; transposed [n][k] rows, fp16 rn,
// 144B row stride, per-chunk images ready for cp.async.bulk.
// ---------------------------------------------------------------------------
__global__ void prep_kernel(const float* __restrict__ conv_w, const float* __restrict__ w1) {
    int p = blockIdx.x;    // k: 0..831
    int h = threadIdx.x;   // n: 0..223
    float s = 0.f;
    if (p < KTOT && h < NHID) {
        int y = p / 28, xx = p % 28;
#pragma unroll
        for (int di = 0; di < 3; ++di) {
            int oy = y - di;
            if (oy < 0 || oy > 25) continue;
#pragma unroll
            for (int dj = 0; dj < 3; ++dj) {
                int ox = xx - dj;
                if (ox < 0 || ox > 25) continue;
                s += conv_w[di * 3 + dj] * w1[(oy * 26 + ox) * NHID + h];
            }
        }
    }
    __half hv = __float2half_rn(s);
    int chunk = p >> 6, kl = p & 63;
    size_t off = (size_t)chunk * BCH + (size_t)h * ROWB + (size_t)kl * 2;
    *(unsigned short*)(g_wB + off) = __half_as_ushort(hv);
}

// Convert 8 fp32 -> 8 fp16 (rn), packed pairs.
__device__ __forceinline__ void cvt8(float4 v0, float4 v1, uint4& hi) {
    __half2 h0 = __floats2half2_rn(v0.x, v0.y);
    __half2 h1 = __floats2half2_rn(v0.z, v0.w);
    __half2 h2 = __floats2half2_rn(v1.x, v1.y);
    __half2 h3 = __floats2half2_rn(v1.z, v1.w);
    hi.x = *reinterpret_cast<uint32_t*>(&h0);
    hi.y = *reinterpret_cast<uint32_t*>(&h1);
    hi.z = *reinterpret_cast<uint32_t*>(&h2);
    hi.w = *reinterpret_cast<uint32_t*>(&h3);
}

// One k16-step of the 32x56 warp tile: 14 MMAs, 4 B-ldsm, 2 A-ldsm.
__device__ __forceinline__ void kstep(uint32_t aB, uint32_t bB, uint32_t kb, float* acc) {
    uint32_t bf[14], ah[8];
    ldsm4(&bf[0],  bB + 0 * (16 * ROWB) + kb);
    ldsm4(&bf[4],  bB + 1 * (16 * ROWB) + kb);
    ldsm4(&bf[8],  bB + 2 * (16 * ROWB) + kb);
    ldsm2(&bf[12], bB + 3 * (16 * ROWB) + kb);
    ldsm4(&ah[0], aB + kb);
    ldsm4(&ah[4], aB + 16 * ROWB + kb);
#pragma unroll
    for (int mt = 0; mt < 2; ++mt)
#pragma unroll
        for (int tn = 0; tn < 7; ++tn)
            mma16816(&acc[mt * 28 + tn * 4], &ah[mt * 4], &bf[tn * 2]);
}

// ---------------------------------------------------------------------------
// Fused: out = relu(X @ W1eff + b1) @ w2 + b2  (plain fp16 mma.sync)
// 16 warps = 4m x 4n; warp tile 32(m) x 56(n). Global x loads for chunk i+1
// issued before the MMA burst of chunk i; convert/store after (latency hidden).
// ---------------------------------------------------------------------------
__global__ __launch_bounds__(NTHREADS, 1)
void fused_mma_kernel(const float* __restrict__ x,
                      const float* __restrict__ b1,
                      const float* __restrict__ w2,
                      const float* __restrict__ b2,
                      float* __restrict__ out) {
    extern __shared__ __align__(1024) unsigned char smem[];
    const uint32_t sb = smem_u32(smem);
    const int tid  = threadIdx.x;
    const int wid  = tid >> 5;
    const int lane = tid & 31;
    const int m0   = blockIdx.x * BM;

    // this thread's two A-granules (m row, k-octet) within a chunk
    const int g_m0 = tid >> 3,          g_g0 = tid & 7;
    const int g_m1 = (tid + 512) >> 3,  g_g1 = tid & 7;

    float* w2s = (float*)(smem + SM_W2);
    float* b1s = (float*)(smem + SM_B1);
    float* b2s = (float*)(smem + SM_B2);

    if (tid == 0) {
        MBARRIER_INIT(sb + SM_MB0, 1);
        MBARRIER_INIT(sb + SM_MB1, 1);
    }
    for (int e = tid; e < NHID * NCLS; e += NTHREADS) w2s[e] = w2[e];
    for (int e = tid; e < NHID; e += NTHREADS)        b1s[e] = b1[e];
    if (tid < NCLS)                                   b2s[tid] = b2[tid];
    __syncthreads();

    const int lg = lane >> 3, lr = lane & 7;
    const uint32_t a_off = (uint32_t)(((lg & 1) * 8 + lr) * ROWB + (lg >> 1) * 16);
    const uint32_t b_off = (uint32_t)(((lg >> 1) * 8 + lr) * ROWB + (lg & 1) * 16);
    const int wm = (wid & 3) * 32;       // 4 m-warps
    const int wn = (wid >> 2) * 56;      // 4 n-warps

    float acc[56];
#pragma unroll
    for (int i = 0; i < 56; ++i) acc[i] = 0.f;

    // ---------------- prologue: B(0) in flight, A(0) converted ----------------
    if (tid == 0) {
        MBARRIER_EXPECT_TX(sb + SM_MB0, BCH);
        bulk_g2s(sb + SM_B(0), g_wB, BCH, sb + SM_MB0);
    }
    {
        unsigned char* Ahi = smem + SM_A(0);
        const float4* s0 = (const float4*)(x + (size_t)(m0 + g_m0) * KTOT + g_g0 * 8);
        const float4* s1 = (const float4*)(x + (size_t)(m0 + g_m1) * KTOT + g_g1 * 8);
        uint4 hi;
        cvt8(s0[0], s0[1], hi);
        *(uint4*)(Ahi + (uint32_t)g_m0 * ROWB + (uint32_t)g_g0 * 16) = hi;
        cvt8(s1[0], s1[1], hi);
        *(uint4*)(Ahi + (uint32_t)g_m1 * ROWB + (uint32_t)g_g1 * 16) = hi;
    }
    __syncthreads();

    // ---------------- main loop ----------------
#pragma unroll 1
    for (int i = 0; i < NCHUNK; ++i) {
        const int s = i & 1;
        const bool hasNext = (i + 1 < NCHUNK);

        // issue B(i+1) into the other buffer (freed by last iteration's sync)
        if (hasNext && tid == 0) {
            const uint32_t mb = sb + (s ? SM_MB0 : SM_MB1);
            MBARRIER_EXPECT_TX(mb, BCH);
            bulk_g2s(sb + SM_B(1 - s), g_wB + (size_t)(i + 1) * BCH, BCH, mb);
        }

        // issue global x loads for chunk i+1 (latency hidden behind MMAs)
        float4 p0a, p0b, p1a, p1b;
        bool val0 = false, val1 = false;
        if (hasNext) {
            const int k0n = (i + 1) * BK;
            const int kg0 = k0n + g_g0 * 8;
            const int kg1 = k0n + g_g1 * 8;
            val0 = kg0 < KTOT;
            val1 = kg1 < KTOT;
            if (val0) {
                const float4* src = (const float4*)(x + (size_t)(m0 + g_m0) * KTOT + kg0);
                p0a = src[0]; p0b = src[1];
            }
            if (val1) {
                const float4* src = (const float4*)(x + (size_t)(m0 + g_m1) * KTOT + kg1);
                p1a = src[0]; p1b = src[1];
            }
        }

        // wait for B(i)
        MBARRIER_WAIT_PARITY(sb + (s ? SM_MB1 : SM_MB0), (i >> 1) & 1);

        const uint32_t aB = sb + SM_A(s) + (uint32_t)wm * ROWB + a_off;
        const uint32_t bB = sb + SM_B(s) + (uint32_t)wn * ROWB + b_off;

        if (i != NCHUNK - 1) {
            kstep(aB, bB, 0,  acc);
            kstep(aB, bB, 32, acc);
            kstep(aB, bB, 64, acc);
            kstep(aB, bB, 96, acc);
        } else {
            kstep(aB, bB, 0, acc);   // 784 = 12*64 + 16
        }

        // convert + store A(i+1) into the other stage
        if (hasNext) {
            unsigned char* Ahi = smem + SM_A(1 - s);
            uint4 hi = {0, 0, 0, 0};
            if (val0) cvt8(p0a, p0b, hi);
            *(uint4*)(Ahi + (uint32_t)g_m0 * ROWB + (uint32_t)g_g0 * 16) = hi;
            uint4 hi1 = {0, 0, 0, 0};
            if (val1) cvt8(p1a, p1b, hi1);
            *(uint4*)(Ahi + (uint32_t)g_m1 * ROWB + (uint32_t)g_g1 * 16) = hi1;
        }
        __syncthreads();
    }

    // ---------------- epilogue: relu(+b1) -> smem, then @ w2 + b2 ----------------
    float* hid  = (float*)(smem + SM_HID);    // [128][210]
    float* outp = (float*)(smem + SM_OUTP);   // [128][10]

#pragma unroll
    for (int mt = 0; mt < 2; ++mt) {
#pragma unroll
        for (int tn = 0; tn < 7; ++tn) {
            int c = wn + tn * 8 + (lane & 3) * 2;
            if (c < NHID) {
                int r0 = wm + mt * 16 + (lane >> 2);
                float b1a = b1s[c], b1b = b1s[c + 1];
                const float* a = &acc[mt * 28 + tn * 4];
                hid[r0 * HSTRIDE + c]           = fmaxf(a[0] + b1a, 0.f);
                hid[r0 * HSTRIDE + c + 1]       = fmaxf(a[1] + b1b, 0.f);
                hid[(r0 + 8) * HSTRIDE + c]     = fmaxf(a[2] + b1a, 0.f);
                hid[(r0 + 8) * HSTRIDE + c + 1] = fmaxf(a[3] + b1b, 0.f);
            }
        }
    }
    for (int e = tid; e < BM * NCLS; e += NTHREADS) outp[e] = 0.f;
    __syncthreads();

    {
        int m  = tid >> 2;                  // 0..127
        int h0 = (tid & 3) * 50;            // 4 k-slices of 50
        float p[NCLS];
#pragma unroll
        for (int c = 0; c < NCLS; ++c) p[c] = 0.f;
        for (int h = h0; h < h0 + 50; ++h) {
            float v = hid[m * HSTRIDE + h];
#pragma unroll
            for (int c = 0; c < NCLS; ++c) p[c] += v * w2s[h * NCLS + c];
        }
#pragma unroll
        for (int c = 0; c < NCLS; ++c) atomicAdd(&outp[m * NCLS + c], p[c]);
    }
    __syncthreads();

    for (int e = tid; e < BM * NCLS; e += NTHREADS)
        out[(size_t)m0 * NCLS + e] = outp[e] + b2s[e % NCLS];
}

// ---------------------------------------------------------------------------
extern "C" void kernel_launch(void* const* d_in, const int* in_sizes, int n_in,
                              void* d_out, int out_size) {
    const float* x      = (const float*)d_in[0];   // [65536, 784]
    const float* conv_w = (const float*)d_in[1];   // [3, 3]
    const float* w1     = (const float*)d_in[2];   // [676, 200]
    const float* b1     = (const float*)d_in[3];   // [200]
    const float* w2     = (const float*)d_in[4];   // [200, 10]
    const float* b2     = (const float*)d_in[5];   // [10]
    float* out          = (float*)d_out;           // [65536, 10]

    cudaFuncSetAttribute(fused_mma_kernel,
                         cudaFuncAttributeMaxDynamicSharedMemorySize, SMEM_TOTAL);

    prep_kernel<<<NCHUNK * BK, NPAD>>>(conv_w, w1);
    fused_mma_kernel<<<65536 / BM, NTHREADS, SMEM_TOTAL>>>(x, b1, w2, b2, out);
}

// round 9
// speedup vs baseline: 2.6167x; 1.0171x over previous
#include <cuda_runtime.h>
#include <cuda_fp16.h>
#include <cstdint>

// ---------------- problem constants ----------------
#define KTOT 784            // 28*28 GEMM K
#define NHID 200            // hidden width
#define NPAD 216            // 3 n-warps x 72
#define NCLS 10
#define BM   128            // rows per CTA
#define BK   64             // K per chunk
#define NCHUNK 13           // 12*64 + 16 (last chunk: 1 k-step)
#define ROWB 144            // bytes per fp16 row -> LDSM conflict-free
#define ACH  (BM * ROWB)    // 18432
#define BRES (NPAD * ROWB)  // 31104 reserved (ldsm reach)
#define BCPY (NHID * ROWB)  // 28800 actually copied
#define NTHREADS 384        // 12 warps = 4m x 3n

// ---------------- smem layout (bytes) ----------------
#define SM_MB0   0
#define SM_MB1   8
#define SM_W2    64                         // 2000 floats
#define SM_B1    8064                       // 200 floats
#define SM_B2    8864                       // 10 floats
#define SM_ABASE 9216
#define SM_A(s)  (SM_ABASE + (s) * ACH)                        // 2 x 18432
#define SM_BBASE (SM_ABASE + 2 * ACH)                          // 46080
#define SM_B(s)  (SM_BBASE + (s) * BRES)                       // 2 x 31104
#define SM_STAGE (SM_BBASE + 2 * BRES)                         // 108288, 32KB fp32
#define SMEM_TOTAL (SM_STAGE + BM * BK * 4)                    // 141056
// epilogue reuse
#define SM_HID   9216                       // 128 x 210 floats
#define HSTRIDE  210
#define SM_OUTP  (SM_HID + BM * HSTRIDE * 4)                   // 116736

// Per-chunk images of W1eff^T (n-major rows, 144B stride) in fp16, 200 rows.
__device__ __align__(16) unsigned char g_wB[NCHUNK * BCPY];

// ---------------- PTX helpers ----------------
__device__ __forceinline__ uint32_t smem_u32(const void* p) {
    uint32_t a;
    asm("{ .reg .u64 t; cvta.to.shared.u64 t, %1; cvt.u32.u64 %0, t; }" : "=r"(a) : "l"(p));
    return a;
}

#define MBARRIER_INIT(a, n) \
    asm volatile("mbarrier.init.shared.b64 [%0], %1;" :: "r"(a), "r"((uint32_t)(n)) : "memory")
#define MBARRIER_EXPECT_TX(a, b) \
    asm volatile("mbarrier.arrive.expect_tx.shared.b64 _, [%0], %1;" :: "r"(a), "r"((uint32_t)(b)) : "memory")

#define MBARRIER_WAIT_PARITY(mbar, par) do {                                   \
    uint32_t _m = (mbar), _p = (par), _d;                                      \
    asm volatile("{\n\t.reg .pred p;\n\t"                                      \
        "mbarrier.try_wait.parity.acquire.cta.shared::cta.b64 p, [%1], %2;\n\t"\
        "selp.b32 %0, 1, 0, p;\n\t}"                                           \
        : "=r"(_d) : "r"(_m), "r"(_p) : "memory");                             \
    if (!_d) {                                                                 \
        asm volatile("{\n\t.reg .pred P1;\n\t"                                 \
            "W%=:\n\t"                                                         \
            "mbarrier.try_wait.parity.acquire.cta.shared::cta.b64 P1, [%0], %1, 0x989680;\n\t" \
            "@P1 bra.uni D%=;\n\t"                                             \
            "bra.uni W%=;\n\t"                                                 \
            "D%=:\n\t}" :: "r"(_m), "r"(_p) : "memory");                       \
    }                                                                          \
} while (0)

__device__ __forceinline__ void bulk_g2s(uint32_t dst, const void* src, uint32_t bytes, uint32_t mbar) {
    asm volatile("cp.async.bulk.shared::cta.global.mbarrier::complete_tx::bytes [%0], [%1], %2, [%3];"
        :: "r"(dst), "l"(src), "r"(bytes), "r"(mbar) : "memory");
}
__device__ __forceinline__ void cp_async16(uint32_t dst, const void* src) {
    asm volatile("cp.async.cg.shared.global [%0], [%1], 16;" :: "r"(dst), "l"(src) : "memory");
}
#define CP_COMMIT() asm volatile("cp.async.commit_group;" ::: "memory")
#define CP_WAIT0()  asm volatile("cp.async.wait_group 0;" ::: "memory")

__device__ __forceinline__ void ldsm4(uint32_t* d, uint32_t addr) {
    asm volatile("ldmatrix.sync.aligned.m8n8.x4.shared.b16 {%0,%1,%2,%3}, [%4];"
        : "=r"(d[0]), "=r"(d[1]), "=r"(d[2]), "=r"(d[3]) : "r"(addr));
}
__device__ __forceinline__ void ldsm2(uint32_t* d, uint32_t addr) {
    asm volatile("ldmatrix.sync.aligned.m8n8.x2.shared.b16 {%0,%1}, [%2];"
        : "=r"(d[0]), "=r"(d[1]) : "r"(addr));
}
__device__ __forceinline__ void mma16816(float* c, const uint32_t* a, const uint32_t* b) {
    asm volatile("mma.sync.aligned.m16n8k16.row.col.f32.f16.f16.f32 "
        "{%0,%1,%2,%3}, {%4,%5,%6,%7}, {%8,%9}, {%0,%1,%2,%3};"
        : "+f"(c[0]), "+f"(c[1]), "+f"(c[2]), "+f"(c[3])
        : "r"(a[0]), "r"(a[1]), "r"(a[2]), "r"(a[3]), "r"(b[0]), "r"(b[1]));
}

// ---------------------------------------------------------------------------
// Prep: W1eff[k][n], conv folded into w1; transposed [n][k] fp16 rows (144B),
// per-chunk images of exactly 200 rows.
// ---------------------------------------------------------------------------
__global__ void prep_kernel(const float* __restrict__ conv_w, const float* __restrict__ w1) {
    int p = blockIdx.x;    // k: 0..831
    int h = threadIdx.x;   // n: 0..199
    float s = 0.f;
    if (p < KTOT) {
        int y = p / 28, xx = p % 28;
#pragma unroll
        for (int di = 0; di < 3; ++di) {
            int oy = y - di;
            if (oy < 0 || oy > 25) continue;
#pragma unroll
            for (int dj = 0; dj < 3; ++dj) {
                int ox = xx - dj;
                if (ox < 0 || ox > 25) continue;
                s += conv_w[di * 3 + dj] * w1[(oy * 26 + ox) * NHID + h];
            }
        }
    }
    __half hv = __float2half_rn(s);
    int chunk = p >> 6, kl = p & 63;
    size_t off = (size_t)chunk * BCPY + (size_t)h * ROWB + (size_t)kl * 2;
    *(unsigned short*)(g_wB + off) = __half_as_ushort(hv);
}

// Convert 8 fp32 -> 8 fp16 (rn), packed pairs.
__device__ __forceinline__ void cvt8(float4 v0, float4 v1, uint4& hi) {
    __half2 h0 = __floats2half2_rn(v0.x, v0.y);
    __half2 h1 = __floats2half2_rn(v0.z, v0.w);
    __half2 h2 = __floats2half2_rn(v1.x, v1.y);
    __half2 h3 = __floats2half2_rn(v1.z, v1.w);
    hi.x = *reinterpret_cast<uint32_t*>(&h0);
    hi.y = *reinterpret_cast<uint32_t*>(&h1);
    hi.z = *reinterpret_cast<uint32_t*>(&h2);
    hi.w = *reinterpret_cast<uint32_t*>(&h3);
}

// Fragment load: one k16 slice of the 32x72 warp tile (18 B-regs, 8 A-regs).
__device__ __forceinline__ void ld_frags(uint32_t aB, uint32_t bB, uint32_t kb,
                                         uint32_t* bf, uint32_t* ah) {
    ldsm4(&bf[0],  bB + 0 * (16 * ROWB) + kb);
    ldsm4(&bf[4],  bB + 1 * (16 * ROWB) + kb);
    ldsm4(&bf[8],  bB + 2 * (16 * ROWB) + kb);
    ldsm4(&bf[12], bB + 3 * (16 * ROWB) + kb);
    ldsm2(&bf[16], bB + 4 * (16 * ROWB) + kb);
    ldsm4(&ah[0], aB + kb);
    ldsm4(&ah[4], aB + 16 * ROWB + kb);
}
// 18 MMAs on one fragment set.
__device__ __forceinline__ void mma_frags(const uint32_t* bf, const uint32_t* ah, float* acc) {
#pragma unroll
    for (int mt = 0; mt < 2; ++mt)
#pragma unroll
        for (int tn = 0; tn < 9; ++tn)
            mma16816(&acc[mt * 36 + tn * 4], &ah[mt * 4], &bf[tn * 2]);
}

// ---------------------------------------------------------------------------
// Fused: out = relu(X @ W1eff + b1) @ w2 + b2  (plain fp16 mma.sync)
// 12 warps = 4m x 3n; warp tile 32x72. Fragments double-buffered across
// k-steps; A staged via cp.async and converted after the MMA burst.
// ---------------------------------------------------------------------------
__global__ __launch_bounds__(NTHREADS, 1)
void fused_mma_kernel(const float* __restrict__ x,
                      const float* __restrict__ b1,
                      const float* __restrict__ w2,
                      const float* __restrict__ b2,
                      float* __restrict__ out) {
    extern __shared__ __align__(1024) unsigned char smem[];
    const uint32_t sb = smem_u32(smem);
    const int tid  = threadIdx.x;
    const int wid  = tid >> 5;
    const int lane = tid & 31;
    const int m0   = blockIdx.x * BM;

    float* w2s = (float*)(smem + SM_W2);
    float* b1s = (float*)(smem + SM_B1);
    float* b2s = (float*)(smem + SM_B2);

    if (tid == 0) {
        MBARRIER_INIT(sb + SM_MB0, 1);
        MBARRIER_INIT(sb + SM_MB1, 1);
    }
    for (int e = tid; e < NHID * NCLS; e += NTHREADS) w2s[e] = w2[e];
    for (int e = tid; e < NHID; e += NTHREADS)        b1s[e] = b1[e];
    if (tid < NCLS)                                   b2s[tid] = b2[tid];
    // zero B rows 200..215 of both stages (never copied; must not be NaN)
    for (int e = tid; e < 2 * (NPAD - NHID) * ROWB / 4; e += NTHREADS) {
        int s = e >= (NPAD - NHID) * ROWB / 4;
        int w = e - s * ((NPAD - NHID) * ROWB / 4);
        *(uint32_t*)(smem + SM_B(s) + BCPY + w * 4) = 0;
    }
    __syncthreads();

    const int lg = lane >> 3, lr = lane & 7;
    const uint32_t a_off = (uint32_t)(((lg & 1) * 8 + lr) * ROWB + (lg >> 1) * 16);
    const uint32_t b_off = (uint32_t)(((lg >> 1) * 8 + lr) * ROWB + (lg & 1) * 16);
    const int wm = (wid & 3) * 32;       // 4 m-warps
    const int wn = (wid >> 2) * 72;      // 3 n-warps

    float acc[72];
#pragma unroll
    for (int i = 0; i < 72; ++i) acc[i] = 0.f;

    // ---------------- prologue: B(0) bulk, A(0) via cp.async + convert ----------------
    if (tid == 0) {
        MBARRIER_EXPECT_TX(sb + SM_MB0, BCPY);
        bulk_g2s(sb + SM_B(0), g_wB, BCPY, sb + SM_MB0);
    }
#pragma unroll
    for (int it = 0; it < 3; ++it) {
        int g = tid + it * NTHREADS;
        if (g < 1024) {
            int m = g >> 3, gg = g & 7;
            const float* src = x + (size_t)(m0 + m) * KTOT + gg * 8;
            uint32_t dst = sb + SM_STAGE + m * 256 + gg * 32;
            cp_async16(dst, src);
            cp_async16(dst + 16, src + 4);
        }
    }
    CP_COMMIT();
    CP_WAIT0();
#pragma unroll
    for (int it = 0; it < 3; ++it) {
        int g = tid + it * NTHREADS;
        if (g < 1024) {
            int m = g >> 3, gg = g & 7;
            const float4* st = (const float4*)(smem + SM_STAGE + m * 256 + gg * 32);
            uint4 h;
            cvt8(st[0], st[1], h);
            *(uint4*)(smem + SM_A(0) + m * ROWB + gg * 16) = h;
        }
    }
    __syncthreads();

    // ---------------- main loop ----------------
#pragma unroll 1
    for (int i = 0; i < NCHUNK; ++i) {
        const int s = i & 1;
        const bool hasNext = (i + 1 < NCHUNK);

        // issue B(i+1) bulk + x(i+1) cp.async into staging
        if (hasNext) {
            if (tid == 0) {
                const uint32_t mb = sb + (s ? SM_MB0 : SM_MB1);
                MBARRIER_EXPECT_TX(mb, BCPY);
                bulk_g2s(sb + SM_B(1 - s), g_wB + (size_t)(i + 1) * BCPY, BCPY, mb);
            }
            const int k0n = (i + 1) * BK;
#pragma unroll
            for (int it = 0; it < 3; ++it) {
                int g = tid + it * NTHREADS;
                if (g < 1024) {
                    int m = g >> 3, gg = g & 7;
                    int kg = k0n + gg * 8;
                    if (kg < KTOT) {
                        const float* src = x + (size_t)(m0 + m) * KTOT + kg;
                        uint32_t dst = sb + SM_STAGE + m * 256 + gg * 32;
                        cp_async16(dst, src);
                        cp_async16(dst + 16, src + 4);
                    }
                }
            }
        }
        CP_COMMIT();

        // wait for B(i)
        MBARRIER_WAIT_PARITY(sb + (s ? SM_MB1 : SM_MB0), (i >> 1) & 1);

        const uint32_t aB = sb + SM_A(s) + (uint32_t)wm * ROWB + a_off;
        const uint32_t bB = sb + SM_B(s) + (uint32_t)wn * ROWB + b_off;

        // fragment-double-buffered k-steps
        {
            uint32_t bf0[18], ah0[8], bf1[18], ah1[8];
            ld_frags(aB, bB, 0, bf0, ah0);
            if (i != NCHUNK - 1) {
                ld_frags(aB, bB, 32, bf1, ah1);
                mma_frags(bf0, ah0, acc);
                ld_frags(aB, bB, 64, bf0, ah0);
                mma_frags(bf1, ah1, acc);
                ld_frags(aB, bB, 96, bf1, ah1);
                mma_frags(bf0, ah0, acc);
                mma_frags(bf1, ah1, acc);
            } else {
                mma_frags(bf0, ah0, acc);   // 784 = 12*64 + 16
            }
        }

        // convert staged x(i+1) -> A(1-s) fp16
        if (hasNext) {
            CP_WAIT0();
            const int k0n = (i + 1) * BK;
#pragma unroll
            for (int it = 0; it < 3; ++it) {
                int g = tid + it * NTHREADS;
                if (g < 1024) {
                    int m = g >> 3, gg = g & 7;
                    int kg = k0n + gg * 8;
                    uint4 h = {0, 0, 0, 0};
                    if (kg < KTOT) {
                        const float4* st = (const float4*)(smem + SM_STAGE + m * 256 + gg * 32);
                        cvt8(st[0], st[1], h);
                    }
                    *(uint4*)(smem + SM_A(1 - s) + m * ROWB + gg * 16) = h;
                }
            }
        }
        __syncthreads();
    }

    // ---------------- epilogue: relu(+b1) -> smem, then @ w2 + b2 ----------------
    float* hid  = (float*)(smem + SM_HID);    // [128][210]
    float* outp = (float*)(smem + SM_OUTP);   // [128][10]

#pragma unroll
    for (int mt = 0; mt < 2; ++mt) {
#pragma unroll
        for (int tn = 0; tn < 9; ++tn) {
            int c = wn + tn * 8 + (lane & 3) * 2;
            if (c < NHID) {
                int r0 = wm + mt * 16 + (lane >> 2);
                float b1a = b1s[c], b1b = b1s[c + 1];
                const float* a = &acc[mt * 36 + tn * 4];
                hid[r0 * HSTRIDE + c]           = fmaxf(a[0] + b1a, 0.f);
                hid[r0 * HSTRIDE + c + 1]       = fmaxf(a[1] + b1b, 0.f);
                hid[(r0 + 8) * HSTRIDE + c]     = fmaxf(a[2] + b1a, 0.f);
                hid[(r0 + 8) * HSTRIDE + c + 1] = fmaxf(a[3] + b1b, 0.f);
            }
        }
    }
    for (int e = tid; e < BM * NCLS; e += NTHREADS) outp[e] = 0.f;
    __syncthreads();

    {
        int m  = tid & 127;                 // 0..127
        int q  = tid >> 7;                  // 3 k-slices of ~67
        int h0 = q * 67;
        int h1 = (q == 2) ? NHID : h0 + 67;
        float p[NCLS];
#pragma unroll
        for (int c = 0; c < NCLS; ++c) p[c] = 0.f;
        for (int h = h0; h < h1; ++h) {
            float v = hid[m * HSTRIDE + h];
#pragma unroll
            for (int c = 0; c < NCLS; ++c) p[c] += v * w2s[h * NCLS + c];
        }
#pragma unroll
        for (int c = 0; c < NCLS; ++c) atomicAdd(&outp[m * NCLS + c], p[c]);
    }
    __syncthreads();

    for (int e = tid; e < BM * NCLS; e += NTHREADS)
        out[(size_t)m0 * NCLS + e] = outp[e] + b2s[e % NCLS];
}

// ---------------------------------------------------------------------------
extern "C" void kernel_launch(void* const* d_in, const int* in_sizes, int n_in,
                              void* d_out, int out_size) {
    const float* x      = (const float*)d_in[0];   // [65536, 784]
    const float* conv_w = (const float*)d_in[1];   // [3, 3]
    const float* w1     = (const float*)d_in[2];   // [676, 200]
    const float* b1     = (const float*)d_in[3];   // [200]
    const float* w2     = (const float*)d_in[4];   // [200, 10]
    const float* b2     = (const float*)d_in[5];   // [10]
    float* out          = (float*)d_out;           // [65536, 10]

    cudaFuncSetAttribute(fused_mma_kernel,
                         cudaFuncAttributeMaxDynamicSharedMemorySize, SMEM_TOTAL);

    prep_kernel<<<NCHUNK * BK, NHID>>>(conv_w, w1);
    fused_mma_kernel<<<65536 / BM, NTHREADS, SMEM_TOTAL>>>(x, b1, w2, b2, out);
}

// round 10
// speedup vs baseline: 2.7454x; 1.0492x over previous
#include <cuda_runtime.h>
#include <cuda_fp16.h>
#include <cstdint>

// ---------------- problem constants ----------------
#define KTOT 784            // 28*28 GEMM K
#define NHID 200            // hidden width
#define NPAD 224            // 4 n-warps x 56
#define NCLS 10
#define BM   64             // rows per CTA (2 CTAs/SM)
#define BK   64             // K per chunk
#define NCHUNK 13           // 12*64 + 16 (last chunk: 1 k-step)
#define ROWB 144            // bytes per fp16 row -> LDSM conflict-free
#define ACH  (BM * ROWB)    // 9216
#define BRES (NPAD * ROWB)  // 32256 reserved (ldsm reach)
#define BCPY (NHID * ROWB)  // 28800 actually copied
#define NTHREADS 256        // 8 warps = 2m x 4n

// ---------------- smem layout (bytes) ----------------
#define SM_MB0   0
#define SM_MB1   8
#define SM_W2    64                         // 2000 floats
#define SM_B1    8064                       // 200 floats
#define SM_B2    8864                       // 10 floats
#define SM_ABASE 9216
#define SM_A(s)  (SM_ABASE + (s) * ACH)                        // 2 x 9216
#define SM_BBASE (SM_ABASE + 2 * ACH)                          // 27648
#define SM_B(s)  (SM_BBASE + (s) * BRES)                       // 2 x 32256
#define SM_STAGE (SM_BBASE + 2 * BRES)                         // 92160, 16KB fp32
#define SMEM_TOTAL (SM_STAGE + BM * BK * 4)                    // 108544
// epilogue reuse
#define SM_HID   9216                       // 64 x 210 floats
#define HSTRIDE  210
#define SM_OUTP  (SM_HID + BM * HSTRIDE * 4)                   // 62976

// Per-chunk images of W1eff^T (n-major rows, 144B stride) in fp16, 200 rows.
__device__ __align__(16) unsigned char g_wB[NCHUNK * BCPY];

// ---------------- PTX helpers ----------------
__device__ __forceinline__ uint32_t smem_u32(const void* p) {
    uint32_t a;
    asm("{ .reg .u64 t; cvta.to.shared.u64 t, %1; cvt.u32.u64 %0, t; }" : "=r"(a) : "l"(p));
    return a;
}

#define MBARRIER_INIT(a, n) \
    asm volatile("mbarrier.init.shared.b64 [%0], %1;" :: "r"(a), "r"((uint32_t)(n)) : "memory")
#define MBARRIER_EXPECT_TX(a, b) \
    asm volatile("mbarrier.arrive.expect_tx.shared.b64 _, [%0], %1;" :: "r"(a), "r"((uint32_t)(b)) : "memory")

#define MBARRIER_WAIT_PARITY(mbar, par) do {                                   \
    uint32_t _m = (mbar), _p = (par), _d;                                      \
    asm volatile("{\n\t.reg .pred p;\n\t"                                      \
        "mbarrier.try_wait.parity.acquire.cta.shared::cta.b64 p, [%1], %2;\n\t"\
        "selp.b32 %0, 1, 0, p;\n\t}"                                           \
        : "=r"(_d) : "r"(_m), "r"(_p) : "memory");                             \
    if (!_d) {                                                                 \
        asm volatile("{\n\t.reg .pred P1;\n\t"                                 \
            "W%=:\n\t"                                                         \
            "mbarrier.try_wait.parity.acquire.cta.shared::cta.b64 P1, [%0], %1, 0x989680;\n\t" \
            "@P1 bra.uni D%=;\n\t"                                             \
            "bra.uni W%=;\n\t"                                                 \
            "D%=:\n\t}" :: "r"(_m), "r"(_p) : "memory");                       \
    }                                                                          \
} while (0)

__device__ __forceinline__ void bulk_g2s(uint32_t dst, const void* src, uint32_t bytes, uint32_t mbar) {
    asm volatile("cp.async.bulk.shared::cta.global.mbarrier::complete_tx::bytes [%0], [%1], %2, [%3];"
        :: "r"(dst), "l"(src), "r"(bytes), "r"(mbar) : "memory");
}
__device__ __forceinline__ void cp_async16(uint32_t dst, const void* src) {
    asm volatile("cp.async.cg.shared.global [%0], [%1], 16;" :: "r"(dst), "l"(src) : "memory");
}
#define CP_COMMIT() asm volatile("cp.async.commit_group;" ::: "memory")
#define CP_WAIT0()  asm volatile("cp.async.wait_group 0;" ::: "memory")

__device__ __forceinline__ void ldsm4(uint32_t* d, uint32_t addr) {
    asm volatile("ldmatrix.sync.aligned.m8n8.x4.shared.b16 {%0,%1,%2,%3}, [%4];"
        : "=r"(d[0]), "=r"(d[1]), "=r"(d[2]), "=r"(d[3]) : "r"(addr));
}
__device__ __forceinline__ void ldsm2(uint32_t* d, uint32_t addr) {
    asm volatile("ldmatrix.sync.aligned.m8n8.x2.shared.b16 {%0,%1}, [%2];"
        : "=r"(d[0]), "=r"(d[1]) : "r"(addr));
}
__device__ __forceinline__ void mma16816(float* c, const uint32_t* a, const uint32_t* b) {
    asm volatile("mma.sync.aligned.m16n8k16.row.col.f32.f16.f16.f32 "
        "{%0,%1,%2,%3}, {%4,%5,%6,%7}, {%8,%9}, {%0,%1,%2,%3};"
        : "+f"(c[0]), "+f"(c[1]), "+f"(c[2]), "+f"(c[3])
        : "r"(a[0]), "r"(a[1]), "r"(a[2]), "r"(a[3]), "r"(b[0]), "r"(b[1]));
}

// ---------------------------------------------------------------------------
// Prep: W1eff[k][n], conv folded into w1; transposed [n][k] fp16 rows (144B),
// per-chunk images of exactly 200 rows.
// ---------------------------------------------------------------------------
__global__ void prep_kernel(const float* __restrict__ conv_w, const float* __restrict__ w1) {
    int p = blockIdx.x;    // k: 0..831
    int h = threadIdx.x;   // n: 0..199
    float s = 0.f;
    if (p < KTOT) {
        int y = p / 28, xx = p % 28;
#pragma unroll
        for (int di = 0; di < 3; ++di) {
            int oy = y - di;
            if (oy < 0 || oy > 25) continue;
#pragma unroll
            for (int dj = 0; dj < 3; ++dj) {
                int ox = xx - dj;
                if (ox < 0 || ox > 25) continue;
                s += conv_w[di * 3 + dj] * w1[(oy * 26 + ox) * NHID + h];
            }
        }
    }
    __half hv = __float2half_rn(s);
    int chunk = p >> 6, kl = p & 63;
    size_t off = (size_t)chunk * BCPY + (size_t)h * ROWB + (size_t)kl * 2;
    *(unsigned short*)(g_wB + off) = __half_as_ushort(hv);
}

// Convert 8 fp32 -> 8 fp16 (rn), packed pairs.
__device__ __forceinline__ void cvt8(float4 v0, float4 v1, uint4& hi) {
    __half2 h0 = __floats2half2_rn(v0.x, v0.y);
    __half2 h1 = __floats2half2_rn(v0.z, v0.w);
    __half2 h2 = __floats2half2_rn(v1.x, v1.y);
    __half2 h3 = __floats2half2_rn(v1.z, v1.w);
    hi.x = *reinterpret_cast<uint32_t*>(&h0);
    hi.y = *reinterpret_cast<uint32_t*>(&h1);
    hi.z = *reinterpret_cast<uint32_t*>(&h2);
    hi.w = *reinterpret_cast<uint32_t*>(&h3);
}

// One k16-step of the 32x56 warp tile: 14 MMAs, 4 B-ldsm, 2 A-ldsm.
__device__ __forceinline__ void kstep(uint32_t aB, uint32_t bB, uint32_t kb, float* acc) {
    uint32_t bf[14], ah[8];
    ldsm4(&bf[0],  bB + 0 * (16 * ROWB) + kb);
    ldsm4(&bf[4],  bB + 1 * (16 * ROWB) + kb);
    ldsm4(&bf[8],  bB + 2 * (16 * ROWB) + kb);
    ldsm2(&bf[12], bB + 3 * (16 * ROWB) + kb);
    ldsm4(&ah[0], aB + kb);
    ldsm4(&ah[4], aB + 16 * ROWB + kb);
#pragma unroll
    for (int mt = 0; mt < 2; ++mt)
#pragma unroll
        for (int tn = 0; tn < 7; ++tn)
            mma16816(&acc[mt * 28 + tn * 4], &ah[mt * 4], &bf[tn * 2]);
}

// ---------------------------------------------------------------------------
// Fused: out = relu(X @ W1eff + b1) @ w2 + b2  (plain fp16 mma.sync)
// BM=64, 8 warps = 2m x 4n (tile 32x56), 2 CTAs/SM: per-chunk sync/convert
// phases of one CTA hide behind the other CTA's MMA burst.
// ---------------------------------------------------------------------------
__global__ __launch_bounds__(NTHREADS, 2)
void fused_mma_kernel(const float* __restrict__ x,
                      const float* __restrict__ b1,
                      const float* __restrict__ w2,
                      const float* __restrict__ b2,
                      float* __restrict__ out) {
    extern __shared__ __align__(1024) unsigned char smem[];
    const uint32_t sb = smem_u32(smem);
    const int tid  = threadIdx.x;
    const int wid  = tid >> 5;
    const int lane = tid & 31;
    const int m0   = blockIdx.x * BM;

    float* w2s = (float*)(smem + SM_W2);
    float* b1s = (float*)(smem + SM_B1);
    float* b2s = (float*)(smem + SM_B2);

    if (tid == 0) {
        MBARRIER_INIT(sb + SM_MB0, 1);
        MBARRIER_INIT(sb + SM_MB1, 1);
    }
    for (int e = tid; e < NHID * NCLS; e += NTHREADS) w2s[e] = w2[e];
    for (int e = tid; e < NHID; e += NTHREADS)        b1s[e] = b1[e];
    if (tid < NCLS)                                   b2s[tid] = b2[tid];
    // zero B rows 200..223 of both stages (never copied; must not be NaN)
    for (int e = tid; e < 2 * (NPAD - NHID) * ROWB / 4; e += NTHREADS) {
        int s = e >= (NPAD - NHID) * ROWB / 4;
        int w = e - s * ((NPAD - NHID) * ROWB / 4);
        *(uint32_t*)(smem + SM_B(s) + BCPY + w * 4) = 0;
    }
    __syncthreads();

    const int lg = lane >> 3, lr = lane & 7;
    const uint32_t a_off = (uint32_t)(((lg & 1) * 8 + lr) * ROWB + (lg >> 1) * 16);
    const uint32_t b_off = (uint32_t)(((lg >> 1) * 8 + lr) * ROWB + (lg & 1) * 16);
    const int wm = (wid & 1) * 32;       // 2 m-warps
    const int wn = (wid >> 1) * 56;      // 4 n-warps

    float acc[56];
#pragma unroll
    for (int i = 0; i < 56; ++i) acc[i] = 0.f;

    // ---------------- prologue: B(0) bulk, A(0) via cp.async + convert ----------------
    if (tid == 0) {
        MBARRIER_EXPECT_TX(sb + SM_MB0, BCPY);
        bulk_g2s(sb + SM_B(0), g_wB, BCPY, sb + SM_MB0);
    }
#pragma unroll
    for (int it = 0; it < 2; ++it) {
        int g = tid + it * NTHREADS;     // 0..511
        int m = g >> 3, gg = g & 7;
        const float* src = x + (size_t)(m0 + m) * KTOT + gg * 8;
        uint32_t dst = sb + SM_STAGE + m * 256 + gg * 32;
        cp_async16(dst, src);
        cp_async16(dst + 16, src + 4);
    }
    CP_COMMIT();
    CP_WAIT0();
#pragma unroll
    for (int it = 0; it < 2; ++it) {
        int g = tid + it * NTHREADS;
        int m = g >> 3, gg = g & 7;
        const float4* st = (const float4*)(smem + SM_STAGE + m * 256 + gg * 32);
        uint4 h;
        cvt8(st[0], st[1], h);
        *(uint4*)(smem + SM_A(0) + m * ROWB + gg * 16) = h;
    }
    __syncthreads();

    // ---------------- main loop ----------------
#pragma unroll 1
    for (int i = 0; i < NCHUNK; ++i) {
        const int s = i & 1;
        const bool hasNext = (i + 1 < NCHUNK);

        // issue B(i+1) bulk + x(i+1) cp.async into staging
        if (hasNext) {
            if (tid == 0) {
                const uint32_t mb = sb + (s ? SM_MB0 : SM_MB1);
                MBARRIER_EXPECT_TX(mb, BCPY);
                bulk_g2s(sb + SM_B(1 - s), g_wB + (size_t)(i + 1) * BCPY, BCPY, mb);
            }
            const int k0n = (i + 1) * BK;
#pragma unroll
            for (int it = 0; it < 2; ++it) {
                int g = tid + it * NTHREADS;
                int m = g >> 3, gg = g & 7;
                int kg = k0n + gg * 8;
                if (kg < KTOT) {
                    const float* src = x + (size_t)(m0 + m) * KTOT + kg;
                    uint32_t dst = sb + SM_STAGE + m * 256 + gg * 32;
                    cp_async16(dst, src);
                    cp_async16(dst + 16, src + 4);
                }
            }
        }
        CP_COMMIT();

        // wait for B(i)
        MBARRIER_WAIT_PARITY(sb + (s ? SM_MB1 : SM_MB0), (i >> 1) & 1);

        const uint32_t aB = sb + SM_A(s) + (uint32_t)wm * ROWB + a_off;
        const uint32_t bB = sb + SM_B(s) + (uint32_t)wn * ROWB + b_off;

        if (i != NCHUNK - 1) {
            kstep(aB, bB, 0,  acc);
            kstep(aB, bB, 32, acc);
            kstep(aB, bB, 64, acc);
            kstep(aB, bB, 96, acc);
        } else {
            kstep(aB, bB, 0, acc);   // 784 = 12*64 + 16
        }

        // convert staged x(i+1) -> A(1-s) fp16
        if (hasNext) {
            CP_WAIT0();
            const int k0n = (i + 1) * BK;
#pragma unroll
            for (int it = 0; it < 2; ++it) {
                int g = tid + it * NTHREADS;
                int m = g >> 3, gg = g & 7;
                int kg = k0n + gg * 8;
                uint4 h = {0, 0, 0, 0};
                if (kg < KTOT) {
                    const float4* st = (const float4*)(smem + SM_STAGE + m * 256 + gg * 32);
                    cvt8(st[0], st[1], h);
                }
                *(uint4*)(smem + SM_A(1 - s) + m * ROWB + gg * 16) = h;
            }
        }
        __syncthreads();
    }

    // ---------------- epilogue: relu(+b1) -> smem, then @ w2 + b2 ----------------
    float* hid  = (float*)(smem + SM_HID);    // [64][210]
    float* outp = (float*)(smem + SM_OUTP);   // [64][10]

#pragma unroll
    for (int mt = 0; mt < 2; ++mt) {
#pragma unroll
        for (int tn = 0; tn < 7; ++tn) {
            int c = wn + tn * 8 + (lane & 3) * 2;
            if (c < NHID) {
                int r0 = wm + mt * 16 + (lane >> 2);
                float b1a = b1s[c], b1b = b1s[c + 1];
                const float* a = &acc[mt * 28 + tn * 4];
                hid[r0 * HSTRIDE + c]           = fmaxf(a[0] + b1a, 0.f);
                hid[r0 * HSTRIDE + c + 1]       = fmaxf(a[1] + b1b, 0.f);
                hid[(r0 + 8) * HSTRIDE + c]     = fmaxf(a[2] + b1a, 0.f);
                hid[(r0 + 8) * HSTRIDE + c + 1] = fmaxf(a[3] + b1b, 0.f);
            }
        }
    }
    for (int e = tid; e < BM * NCLS; e += NTHREADS) outp[e] = 0.f;
    __syncthreads();

    {
        int m  = tid >> 2;                  // 0..63
        int h0 = (tid & 3) * 50;            // 4 k-slices of 50
        float p[NCLS];
#pragma unroll
        for (int c = 0; c < NCLS; ++c) p[c] = 0.f;
        for (int h = h0; h < h0 + 50; ++h) {
            float v = hid[m * HSTRIDE + h];
#pragma unroll
            for (int c = 0; c < NCLS; ++c) p[c] += v * w2s[h * NCLS + c];
        }
#pragma unroll
        for (int c = 0; c < NCLS; ++c) atomicAdd(&outp[m * NCLS + c], p[c]);
    }
    __syncthreads();

    for (int e = tid; e < BM * NCLS; e += NTHREADS)
        out[(size_t)m0 * NCLS + e] = outp[e] + b2s[e % NCLS];
}

// ---------------------------------------------------------------------------
extern "C" void kernel_launch(void* const* d_in, const int* in_sizes, int n_in,
                              void* d_out, int out_size) {
    const float* x      = (const float*)d_in[0];   // [65536, 784]
    const float* conv_w = (const float*)d_in[1];   // [3, 3]
    const float* w1     = (const float*)d_in[2];   // [676, 200]
    const float* b1     = (const float*)d_in[3];   // [200]
    const float* w2     = (const float*)d_in[4];   // [200, 10]
    const float* b2     = (const float*)d_in[5];   // [10]
    float* out          = (float*)d_out;           // [65536, 10]

    cudaFuncSetAttribute(fused_mma_kernel,
                         cudaFuncAttributeMaxDynamicSharedMemorySize, SMEM_TOTAL);

    prep_kernel<<<NCHUNK * BK, NHID>>>(conv_w, w1);
    fused_mma_kernel<<<65536 / BM, NTHREADS, SMEM_TOTAL>>>(x, b1, w2, b2, out);
}

// round 11
// speedup vs baseline: 2.7911x; 1.0167x over previous
#include <cuda_runtime.h>
#include <cuda_fp16.h>
#include <cstdint>

// ---------------- problem constants ----------------
#define KTOT 784            // 28*28 GEMM K
#define NHID 200            // hidden width
#define NPAD 224            // 4 n-warps x 56
#define NCLS 10
#define BM   64             // rows per CTA (2 CTAs/SM)
#define BK   64             // K per chunk
#define NCHUNK 13           // 12*64 + 16 (last chunk: 1 k-step)
#define ROWB 144            // bytes per fp16 row -> LDSM conflict-free
#define ACH  (BM * ROWB)    // 9216
#define BRES (NPAD * ROWB)  // 32256 reserved (ldsm reach)
#define BCPY (NHID * ROWB)  // 28800 actually copied
#define NTHREADS 256        // 8 warps = 2m x 4n

// ---------------- smem layout (bytes) ----------------
#define SM_MB0   0
#define SM_MB1   8
#define SM_W2    64                         // 2000 floats
#define SM_B1    8064                       // 200 floats
#define SM_B2    8864                       // 10 floats
#define SM_ABASE 9216
#define SM_A(s)  (SM_ABASE + (s) * ACH)                        // 2 x 9216
#define SM_BBASE (SM_ABASE + 2 * ACH)                          // 27648
#define SM_B(s)  (SM_BBASE + (s) * BRES)                       // 2 x 32256
#define SMEM_TOTAL (SM_BBASE + 2 * BRES)                       // 92160
// epilogue reuse
#define SM_HID   9216                       // 64 x 210 floats
#define HSTRIDE  210
#define SM_OUTP  (SM_HID + BM * HSTRIDE * 4)                   // 62976

// Per-chunk images of W1eff^T (n-major rows, 144B stride) in fp16, 200 rows.
__device__ __align__(16) unsigned char g_wB[NCHUNK * BCPY];

// ---------------- PTX helpers ----------------
__device__ __forceinline__ uint32_t smem_u32(const void* p) {
    uint32_t a;
    asm("{ .reg .u64 t; cvta.to.shared.u64 t, %1; cvt.u32.u64 %0, t; }" : "=r"(a) : "l"(p));
    return a;
}

#define MBARRIER_INIT(a, n) \
    asm volatile("mbarrier.init.shared.b64 [%0], %1;" :: "r"(a), "r"((uint32_t)(n)) : "memory")
#define MBARRIER_EXPECT_TX(a, b) \
    asm volatile("mbarrier.arrive.expect_tx.shared.b64 _, [%0], %1;" :: "r"(a), "r"((uint32_t)(b)) : "memory")

#define MBARRIER_WAIT_PARITY(mbar, par) do {                                   \
    uint32_t _m = (mbar), _p = (par), _d;                                      \
    asm volatile("{\n\t.reg .pred p;\n\t"                                      \
        "mbarrier.try_wait.parity.acquire.cta.shared::cta.b64 p, [%1], %2;\n\t"\
        "selp.b32 %0, 1, 0, p;\n\t}"                                           \
        : "=r"(_d) : "r"(_m), "r"(_p) : "memory");                             \
    if (!_d) {                                                                 \
        asm volatile("{\n\t.reg .pred P1;\n\t"                                 \
            "W%=:\n\t"                                                         \
            "mbarrier.try_wait.parity.acquire.cta.shared::cta.b64 P1, [%0], %1, 0x989680;\n\t" \
            "@P1 bra.uni D%=;\n\t"                                             \
            "bra.uni W%=;\n\t"                                                 \
            "D%=:\n\t}" :: "r"(_m), "r"(_p) : "memory");                       \
    }                                                                          \
} while (0)

__device__ __forceinline__ void bulk_g2s(uint32_t dst, const void* src, uint32_t bytes, uint32_t mbar) {
    asm volatile("cp.async.bulk.shared::cta.global.mbarrier::complete_tx::bytes [%0], [%1], %2, [%3];"
        :: "r"(dst), "l"(src), "r"(bytes), "r"(mbar) : "memory");
}

__device__ __forceinline__ void ldsm4(uint32_t* d, uint32_t addr) {
    asm volatile("ldmatrix.sync.aligned.m8n8.x4.shared.b16 {%0,%1,%2,%3}, [%4];"
        : "=r"(d[0]), "=r"(d[1]), "=r"(d[2]), "=r"(d[3]) : "r"(addr));
}
__device__ __forceinline__ void ldsm2(uint32_t* d, uint32_t addr) {
    asm volatile("ldmatrix.sync.aligned.m8n8.x2.shared.b16 {%0,%1}, [%2];"
        : "=r"(d[0]), "=r"(d[1]) : "r"(addr));
}
__device__ __forceinline__ void mma16816(float* c, const uint32_t* a, const uint32_t* b) {
    asm volatile("mma.sync.aligned.m16n8k16.row.col.f32.f16.f16.f32 "
        "{%0,%1,%2,%3}, {%4,%5,%6,%7}, {%8,%9}, {%0,%1,%2,%3};"
        : "+f"(c[0]), "+f"(c[1]), "+f"(c[2]), "+f"(c[3])
        : "r"(a[0]), "r"(a[1]), "r"(a[2]), "r"(a[3]), "r"(b[0]), "r"(b[1]));
}

// ---------------------------------------------------------------------------
// Prep: W1eff[k][n], conv folded into w1; transposed [n][k] fp16 rows (144B),
// per-chunk images of exactly 200 rows.
// ---------------------------------------------------------------------------
__global__ void prep_kernel(const float* __restrict__ conv_w, const float* __restrict__ w1) {
    int p = blockIdx.x;    // k: 0..831
    int h = threadIdx.x;   // n: 0..199
    float s = 0.f;
    if (p < KTOT) {
        int y = p / 28, xx = p % 28;
#pragma unroll
        for (int di = 0; di < 3; ++di) {
            int oy = y - di;
            if (oy < 0 || oy > 25) continue;
#pragma unroll
            for (int dj = 0; dj < 3; ++dj) {
                int ox = xx - dj;
                if (ox < 0 || ox > 25) continue;
                s += conv_w[di * 3 + dj] * w1[(oy * 26 + ox) * NHID + h];
            }
        }
    }
    __half hv = __float2half_rn(s);
    int chunk = p >> 6, kl = p & 63;
    size_t off = (size_t)chunk * BCPY + (size_t)h * ROWB + (size_t)kl * 2;
    *(unsigned short*)(g_wB + off) = __half_as_ushort(hv);
}

// Convert 8 fp32 -> 8 fp16 (rn), packed pairs.
__device__ __forceinline__ void cvt8(float4 v0, float4 v1, uint4& hi) {
    __half2 h0 = __floats2half2_rn(v0.x, v0.y);
    __half2 h1 = __floats2half2_rn(v0.z, v0.w);
    __half2 h2 = __floats2half2_rn(v1.x, v1.y);
    __half2 h3 = __floats2half2_rn(v1.z, v1.w);
    hi.x = *reinterpret_cast<uint32_t*>(&h0);
    hi.y = *reinterpret_cast<uint32_t*>(&h1);
    hi.z = *reinterpret_cast<uint32_t*>(&h2);
    hi.w = *reinterpret_cast<uint32_t*>(&h3);
}

// One k16-step of the 32x56 warp tile: 14 MMAs, 4 B-ldsm, 2 A-ldsm.
__device__ __forceinline__ void kstep(uint32_t aB, uint32_t bB, uint32_t kb, float* acc) {
    uint32_t bf[14], ah[8];
    ldsm4(&bf[0],  bB + 0 * (16 * ROWB) + kb);
    ldsm4(&bf[4],  bB + 1 * (16 * ROWB) + kb);
    ldsm4(&bf[8],  bB + 2 * (16 * ROWB) + kb);
    ldsm2(&bf[12], bB + 3 * (16 * ROWB) + kb);
    ldsm4(&ah[0], aB + kb);
    ldsm4(&ah[4], aB + 16 * ROWB + kb);
#pragma unroll
    for (int mt = 0; mt < 2; ++mt)
#pragma unroll
        for (int tn = 0; tn < 7; ++tn)
            mma16816(&acc[mt * 28 + tn * 4], &ah[mt * 4], &bf[tn * 2]);
}

// ---------------------------------------------------------------------------
// Fused: out = relu(X @ W1eff + b1) @ w2 + b2  (plain fp16 mma.sync)
// BM=64, 8 warps = 2m x 4n (tile 32x56), 2 CTAs/SM. Warp-parity-staggered
// k-step order breaks the LDSM/MMA phase lock so crossbar and tensor pipes
// overlap. x prefetched straight into registers (no staging smem).
// ---------------------------------------------------------------------------
__global__ __launch_bounds__(NTHREADS, 2)
void fused_mma_kernel(const float* __restrict__ x,
                      const float* __restrict__ b1,
                      const float* __restrict__ w2,
                      const float* __restrict__ b2,
                      float* __restrict__ out) {
    extern __shared__ __align__(1024) unsigned char smem[];
    const uint32_t sb = smem_u32(smem);
    const int tid  = threadIdx.x;
    const int wid  = tid >> 5;
    const int lane = tid & 31;
    const int m0   = blockIdx.x * BM;

    // this thread's two A-granules (m row, k-octet) within a chunk
    const int g_m0 = tid >> 3,           g_g0 = tid & 7;   // rows 0..31
    const int g_m1 = (tid + 256) >> 3;                     // rows 32..63

    float* w2s = (float*)(smem + SM_W2);
    float* b1s = (float*)(smem + SM_B1);
    float* b2s = (float*)(smem + SM_B2);

    if (tid == 0) {
        MBARRIER_INIT(sb + SM_MB0, 1);
        MBARRIER_INIT(sb + SM_MB1, 1);
    }
    for (int e = tid; e < NHID * NCLS; e += NTHREADS) w2s[e] = w2[e];
    for (int e = tid; e < NHID; e += NTHREADS)        b1s[e] = b1[e];
    if (tid < NCLS)                                   b2s[tid] = b2[tid];
    // zero B rows 200..223 of both stages (never copied; must not be NaN)
    for (int e = tid; e < 2 * (NPAD - NHID) * ROWB / 4; e += NTHREADS) {
        int s = e >= (NPAD - NHID) * ROWB / 4;
        int w = e - s * ((NPAD - NHID) * ROWB / 4);
        *(uint32_t*)(smem + SM_B(s) + BCPY + w * 4) = 0;
    }
    __syncthreads();

    const int lg = lane >> 3, lr = lane & 7;
    const uint32_t a_off = (uint32_t)(((lg & 1) * 8 + lr) * ROWB + (lg >> 1) * 16);
    const uint32_t b_off = (uint32_t)(((lg >> 1) * 8 + lr) * ROWB + (lg & 1) * 16);
    const int wm = (wid & 1) * 32;       // 2 m-warps
    const int wn = (wid >> 1) * 56;      // 4 n-warps
    const int ks0 = (wid & 1) * 2;       // stagger: odd m-warps start at kstep 2

    float acc[56];
#pragma unroll
    for (int i = 0; i < 56; ++i) acc[i] = 0.f;

    // ---------------- prologue: B(0) bulk, A(0) direct load + convert ----------------
    if (tid == 0) {
        MBARRIER_EXPECT_TX(sb + SM_MB0, BCPY);
        bulk_g2s(sb + SM_B(0), g_wB, BCPY, sb + SM_MB0);
    }
    {
        const float4* s0 = (const float4*)(x + (size_t)(m0 + g_m0) * KTOT + g_g0 * 8);
        const float4* s1 = (const float4*)(x + (size_t)(m0 + g_m1) * KTOT + g_g0 * 8);
        uint4 h;
        cvt8(s0[0], s0[1], h);
        *(uint4*)(smem + SM_A(0) + g_m0 * ROWB + g_g0 * 16) = h;
        cvt8(s1[0], s1[1], h);
        *(uint4*)(smem + SM_A(0) + g_m1 * ROWB + g_g0 * 16) = h;
    }
    __syncthreads();

    // ---------------- main loop ----------------
#pragma unroll 1
    for (int i = 0; i < NCHUNK; ++i) {
        const int s = i & 1;
        const bool hasNext = (i + 1 < NCHUNK);

        // issue B(i+1) bulk into the other buffer (freed by last sync)
        if (hasNext && tid == 0) {
            const uint32_t mb = sb + (s ? SM_MB0 : SM_MB1);
            MBARRIER_EXPECT_TX(mb, BCPY);
            bulk_g2s(sb + SM_B(1 - s), g_wB + (size_t)(i + 1) * BCPY, BCPY, mb);
        }

        // issue global x loads for chunk i+1 (latency hidden behind MMAs)
        float4 p0a, p0b, p1a, p1b;
        bool val = false;
        if (hasNext) {
            const int kg = (i + 1) * BK + g_g0 * 8;
            val = kg < KTOT;
            if (val) {
                const float4* s0 = (const float4*)(x + (size_t)(m0 + g_m0) * KTOT + kg);
                const float4* s1 = (const float4*)(x + (size_t)(m0 + g_m1) * KTOT + kg);
                p0a = s0[0]; p0b = s0[1];
                p1a = s1[0]; p1b = s1[1];
            }
        }

        // wait for B(i)
        MBARRIER_WAIT_PARITY(sb + (s ? SM_MB1 : SM_MB0), (i >> 1) & 1);

        const uint32_t aB = sb + SM_A(s) + (uint32_t)wm * ROWB + a_off;
        const uint32_t bB = sb + SM_B(s) + (uint32_t)wn * ROWB + b_off;

        if (i != NCHUNK - 1) {
            // warp-staggered k-step order: kb = ((j + ks0) & 3) * 32
            kstep(aB, bB, (uint32_t)(((0 + ks0) & 3) * 32), acc);
            kstep(aB, bB, (uint32_t)(((1 + ks0) & 3) * 32), acc);
            kstep(aB, bB, (uint32_t)(((2 + ks0) & 3) * 32), acc);
            kstep(aB, bB, (uint32_t)(((3 + ks0) & 3) * 32), acc);
        } else {
            kstep(aB, bB, 0, acc);   // 784 = 12*64 + 16
        }

        // convert prefetched x(i+1) -> A(1-s) fp16
        if (hasNext) {
            uint4 h = {0, 0, 0, 0};
            if (val) cvt8(p0a, p0b, h);
            *(uint4*)(smem + SM_A(1 - s) + g_m0 * ROWB + g_g0 * 16) = h;
            uint4 h1 = {0, 0, 0, 0};
            if (val) cvt8(p1a, p1b, h1);
            *(uint4*)(smem + SM_A(1 - s) + g_m1 * ROWB + g_g0 * 16) = h1;
        }
        __syncthreads();
    }

    // ---------------- epilogue: relu(+b1) -> smem, then @ w2 + b2 ----------------
    float* hid  = (float*)(smem + SM_HID);    // [64][210]
    float* outp = (float*)(smem + SM_OUTP);   // [64][10]

#pragma unroll
    for (int mt = 0; mt < 2; ++mt) {
#pragma unroll
        for (int tn = 0; tn < 7; ++tn) {
            int c = wn + tn * 8 + (lane & 3) * 2;
            if (c < NHID) {
                int r0 = wm + mt * 16 + (lane >> 2);
                float b1a = b1s[c], b1b = b1s[c + 1];
                const float* a = &acc[mt * 28 + tn * 4];
                hid[r0 * HSTRIDE + c]           = fmaxf(a[0] + b1a, 0.f);
                hid[r0 * HSTRIDE + c + 1]       = fmaxf(a[1] + b1b, 0.f);
                hid[(r0 + 8) * HSTRIDE + c]     = fmaxf(a[2] + b1a, 0.f);
                hid[(r0 + 8) * HSTRIDE + c + 1] = fmaxf(a[3] + b1b, 0.f);
            }
        }
    }
    for (int e = tid; e < BM * NCLS; e += NTHREADS) outp[e] = 0.f;
    __syncthreads();

    {
        int m  = tid >> 2;                  // 0..63
        int h0 = (tid & 3) * 50;            // 4 k-slices of 50
        float p[NCLS];
#pragma unroll
        for (int c = 0; c < NCLS; ++c) p[c] = 0.f;
        for (int h = h0; h < h0 + 50; ++h) {
            float v = hid[m * HSTRIDE + h];
#pragma unroll
            for (int c = 0; c < NCLS; ++c) p[c] += v * w2s[h * NCLS + c];
        }
#pragma unroll
        for (int c = 0; c < NCLS; ++c) atomicAdd(&outp[m * NCLS + c], p[c]);
    }
    __syncthreads();

    for (int e = tid; e < BM * NCLS; e += NTHREADS)
        out[(size_t)m0 * NCLS + e] = outp[e] + b2s[e % NCLS];
}

// ---------------------------------------------------------------------------
extern "C" void kernel_launch(void* const* d_in, const int* in_sizes, int n_in,
                              void* d_out, int out_size) {
    const float* x      = (const float*)d_in[0];   // [65536, 784]
    const float* conv_w = (const float*)d_in[1];   // [3, 3]
    const float* w1     = (const float*)d_in[2];   // [676, 200]
    const float* b1     = (const float*)d_in[3];   // [200]
    const float* w2     = (const float*)d_in[4];   // [200, 10]
    const float* b2     = (const float*)d_in[5];   // [10]
    float* out          = (float*)d_out;           // [65536, 10]

    cudaFuncSetAttribute(fused_mma_kernel,
                         cudaFuncAttributeMaxDynamicSharedMemorySize, SMEM_TOTAL);

    prep_kernel<<<NCHUNK * BK, NHID>>>(conv_w, w1);
    fused_mma_kernel<<<65536 / BM, NTHREADS, SMEM_TOTAL>>>(x, b1, w2, b2, out);
}